// round 5
// baseline (speedup 1.0000x reference)
#include <cuda_runtime.h>
#include <cuda_fp16.h>
#include <cstdint>

#define WIN 49
#define HEADS 12
#define HD 32
#define DIMC 384
#define BATCH 4096
#define NWIN 64
#define QKVC (3 * DIMC)     // 1152
#define MROWS (BATCH * WIN) // 200704
#define KTOT 384

// ---------------- scratch (allocation-free rule: __device__ globals) -------
__device__ float g_qkv[(size_t)MROWS * QKVC]; // [B*49, 1152]
__device__ float g_att[(size_t)MROWS * DIMC]; // [B*49, 384]
__device__ __half g_wqkv_hi[QKVC * KTOT]; // W^T qkv, [N=1152][K=384]
__device__ __half g_wqkv_lo[QKVC * KTOT];
__device__ __half g_wprj_hi[DIMC * KTOT]; // W^T proj, [N=384][K=384]
__device__ __half g_wprj_lo[DIMC * KTOT];

// ---------------- helpers ---------------------------------------------------
__device__ __forceinline__ uint32_t smem_u32(const void* p) {
    uint32_t a;
    asm("{ .reg .u64 t; cvta.to.shared.u64 t, %1; cvt.u32.u64 %0, t; }" : "=r"(a) : "l"(p));
    return a;
}
__device__ __forceinline__ uint32_t pack2_f16(float even, float odd) {
    uint32_t r;
    asm("cvt.rn.f16x2.f32 %0, %1, %2;" : "=r"(r) : "f"(odd), "f"(even));
    return r;
}
__device__ __forceinline__ void ldmx4(uint32_t& r0, uint32_t& r1, uint32_t& r2, uint32_t& r3,
                                      uint32_t addr) {
    asm volatile("ldmatrix.sync.aligned.m8n8.x4.shared.b16 {%0,%1,%2,%3}, [%4];"
                 : "=r"(r0), "=r"(r1), "=r"(r2), "=r"(r3) : "r"(addr));
}
__device__ __forceinline__ void mma16816(float* d, uint32_t a0, uint32_t a1, uint32_t a2,
                                         uint32_t a3, uint32_t b0, uint32_t b1) {
    asm volatile(
        "mma.sync.aligned.m16n8k16.row.col.f32.f16.f16.f32 "
        "{%0,%1,%2,%3}, {%4,%5,%6,%7}, {%8,%9}, {%0,%1,%2,%3};"
        : "+f"(d[0]), "+f"(d[1]), "+f"(d[2]), "+f"(d[3])
        : "r"(a0), "r"(a1), "r"(a2), "r"(a3), "r"(b0), "r"(b1));
}
__device__ __forceinline__ void cp_async16(uint32_t saddr, const void* gaddr) {
    asm volatile("cp.async.cg.shared.global [%0], [%1], 16;" :: "r"(saddr), "l"(gaddr) : "memory");
}

// ---------------------------------------------------------------------------
// Weight prep: W [K][N] fp32 -> Wt_hi/Wt_lo [N][K] fp16 (hi + residual lo)
// ---------------------------------------------------------------------------
__global__ void prep_w_kernel(const float* __restrict__ W,
                              __half* __restrict__ hi,
                              __half* __restrict__ lo, int K, int N) {
    int idx = blockIdx.x * 256 + threadIdx.x;
    if (idx >= K * N) return;
    int k = idx / N, n = idx % N;
    float f = W[idx];
    __half h = __float2half_rn(f);
    float hf = __half2float(h);
    __half l = __float2half_rn(f - hf);
    hi[(size_t)n * K + k] = h;
    lo[(size_t)n * K + k] = l;
}

// ---------------------------------------------------------------------------
// 2-term fp16 GEMM via mma.sync, double-buffered smem pipeline.
// CTA 128x128, K-chunk 64, 8 warps (warp tile 64x32). Pitch 144B.
// ---------------------------------------------------------------------------
#define BM 128
#define BN 128
#define KC 64
#define NCHUNK (KTOT / KC)  // 6
#define PITCHB 144
#define TILEB (128 * PITCHB)      // 18432
#define STAGEB (3 * TILEB)        // 55296 per stage (A, Wh, Wl)
#define Ab  0
#define BHb TILEB
#define BLb (2 * TILEB)
#define GEMM_SMEM (2 * STAGEB)    // 110592

__global__ __launch_bounds__(256, 2)
void gemm_tc_kernel(const float* __restrict__ A,
                    const __half* __restrict__ Bhi,
                    const __half* __restrict__ Blo,
                    const float* __restrict__ bias, float* __restrict__ C,
                    int Nout, int scale_cols, float scale) {
    extern __shared__ char smem[];
    const uint32_t sb = smem_u32(smem);
    const int tid = threadIdx.x;
    const int warp = tid >> 5, lane = tid & 31;
    const int wm = warp >> 2;
    const int wn = warp & 3;
    const int bm = blockIdx.y * BM, bn = blockIdx.x * BN;

    float acc[4][4][4];
#pragma unroll
    for (int i = 0; i < 4; i++)
#pragma unroll
        for (int j = 0; j < 4; j++)
#pragma unroll
            for (int r = 0; r < 4; r++) acc[i][j][r] = 0.f;

    const float* Abase = A + (size_t)bm * KTOT;

    const int a_r = lane & 15;
    const int a_c = (lane >> 4) * 16;
    const int b_lrow = lane & 7;
    const int b_q = lane >> 3;
    const int b_noff = ((b_q >> 1) * 8) + b_lrow;
    const int b_koff = (b_q & 1) * 16;

    // per-thread load geometry (index i in 0..7): g = tid + 256*i
    //   W tiles:  t = g>=1024; r=g&1023; row=r>>3; k8=r&7
    //   A tile:   row = g>>4; k4 = g&15

    // ---- prologue: fill stage 0 with chunk 0 ----
#pragma unroll
    for (int i = 0; i < 8; i++) {
        int g = tid + 256 * i;
        int t = (g >= 1024);
        int r = g & 1023;
        int row = r >> 3, k8 = r & 7;
        const __half* src = (t ? Blo : Bhi) + ((size_t)(bn + row) * KTOT + k8 * 8);
        cp_async16(sb + (t ? BLb : BHb) + row * PITCHB + k8 * 16, src);
    }
    asm volatile("cp.async.commit_group;" ::: "memory");
#pragma unroll
    for (int i = 0; i < 8; i++) {
        int g = tid + 256 * i;
        int row = g >> 4, k4 = g & 15;
        float4 f = *(const float4*)(Abase + (size_t)row * KTOT + k4 * 4);
        uint32_t h0 = pack2_f16(f.x, f.y), h1 = pack2_f16(f.z, f.w);
        asm volatile("st.shared.v2.b32 [%0], {%1,%2};"
                     :: "r"(sb + Ab + row * PITCHB + k4 * 8), "r"(h0), "r"(h1) : "memory");
    }
    asm volatile("cp.async.wait_group 0;" ::: "memory");
    __syncthreads();

    for (int c = 0; c < NCHUNK; c++) {
        const uint32_t sp = sb + (uint32_t)(c & 1) * STAGEB;        // compute stage
        const uint32_t sq = sb + (uint32_t)((c & 1) ^ 1) * STAGEB;  // prefetch stage
        const bool pf = (c + 1 < NCHUNK);
        const int kn = (c + 1) * KC;

        // issue next W tiles into idle stage
        if (pf) {
#pragma unroll
            for (int i = 0; i < 8; i++) {
                int g = tid + 256 * i;
                int t = (g >= 1024);
                int r = g & 1023;
                int row = r >> 3, k8 = r & 7;
                const __half* src =
                    (t ? Blo : Bhi) + ((size_t)(bn + row) * KTOT + kn + k8 * 8);
                cp_async16(sq + (t ? BLb : BHb) + row * PITCHB + k8 * 16, src);
            }
            asm volatile("cp.async.commit_group;" ::: "memory");
        }

        // compute 4 k16 steps, interleaved with next-A quarters
#pragma unroll
        for (int kk = 0; kk < 4; kk++) {
            float4 f0, f1;
            int row0 = 0, k40 = 0, row1 = 0, k41 = 0;
            if (pf) {
                int g0 = tid + 256 * (2 * kk);
                int g1 = tid + 256 * (2 * kk + 1);
                row0 = g0 >> 4; k40 = g0 & 15;
                row1 = g1 >> 4; k41 = g1 & 15;
                f0 = *(const float4*)(Abase + (size_t)row0 * KTOT + kn + k40 * 4);
                f1 = *(const float4*)(Abase + (size_t)row1 * KTOT + kn + k41 * 4);
            }

            const uint32_t kbyte = kk * 32;
            uint32_t Ar[4][4], Bh[2][4], Bl[2][4];
#pragma unroll
            for (int mt = 0; mt < 4; mt++) {
                uint32_t ad = sp + Ab + (wm * 64 + mt * 16 + a_r) * PITCHB + kbyte + a_c;
                ldmx4(Ar[mt][0], Ar[mt][1], Ar[mt][2], Ar[mt][3], ad);
            }
#pragma unroll
            for (int p = 0; p < 2; p++) {
                uint32_t bd = sp + (wn * 32 + p * 16 + b_noff) * PITCHB + kbyte + b_koff;
                ldmx4(Bh[p][0], Bh[p][1], Bh[p][2], Bh[p][3], bd + BHb);
                ldmx4(Bl[p][0], Bl[p][1], Bl[p][2], Bl[p][3], bd + BLb);
            }
#pragma unroll
            for (int mt = 0; mt < 4; mt++)
#pragma unroll
                for (int nt = 0; nt < 4; nt++) {
                    const int p = nt >> 1, h = (nt & 1) * 2;
                    mma16816(acc[mt][nt], Ar[mt][0], Ar[mt][1], Ar[mt][2], Ar[mt][3],
                             Bh[p][h], Bh[p][h + 1]);
                    mma16816(acc[mt][nt], Ar[mt][0], Ar[mt][1], Ar[mt][2], Ar[mt][3],
                             Bl[p][h], Bl[p][h + 1]);
                }

            if (pf) {
                uint32_t h0 = pack2_f16(f0.x, f0.y), h1 = pack2_f16(f0.z, f0.w);
                uint32_t h2 = pack2_f16(f1.x, f1.y), h3 = pack2_f16(f1.z, f1.w);
                asm volatile("st.shared.v2.b32 [%0], {%1,%2};"
                             :: "r"(sq + Ab + row0 * PITCHB + k40 * 8), "r"(h0), "r"(h1) : "memory");
                asm volatile("st.shared.v2.b32 [%0], {%1,%2};"
                             :: "r"(sq + Ab + row1 * PITCHB + k41 * 8), "r"(h2), "r"(h3) : "memory");
            }
        }

        asm volatile("cp.async.wait_group 0;" ::: "memory");
        __syncthreads();
    }

    // --- epilogue ---
    const int gid = lane >> 2, tig = lane & 3;
#pragma unroll
    for (int mt = 0; mt < 4; mt++) {
        const int row = bm + wm * 64 + mt * 16 + gid;
#pragma unroll
        for (int nt = 0; nt < 4; nt++) {
            const int col = bn + wn * 32 + nt * 8 + tig * 2;
            const float b0 = bias[col], b1 = bias[col + 1];
            const float s = (col < scale_cols) ? scale : 1.0f;
            float2 v0 = make_float2((acc[mt][nt][0] + b0) * s, (acc[mt][nt][1] + b1) * s);
            float2 v1 = make_float2((acc[mt][nt][2] + b0) * s, (acc[mt][nt][3] + b1) * s);
            *(float2*)(C + (size_t)row * Nout + col) = v0;
            *(float2*)(C + (size_t)(row + 8) * Nout + col) = v1;
        }
    }
}

// ---------------------------------------------------------------------------
// Fused attention per (window b, head h) — unchanged (fp32)
// ---------------------------------------------------------------------------
__global__ __launch_bounds__(256) void attn_kernel(
    const float* __restrict__ qkv, const float* __restrict__ mask,
    const float* __restrict__ bias_table, const int* __restrict__ rel_index,
    float* __restrict__ out) {
    const int b = blockIdx.x;
    const int h = blockIdx.y;

    __shared__ float qs[WIN][HD + 1];
    __shared__ float ks[WIN][HD + 1];
    __shared__ float vs[WIN][HD + 1];
    __shared__ float bi[WIN][WIN];
    __shared__ float pr[8][WIN];

    const int tid = threadIdx.x;
    const float* base = qkv + (size_t)b * WIN * QKVC + h * HD;

    for (int idx = tid; idx < WIN * HD; idx += 256) {
        int i = idx >> 5, d = idx & 31;
        qs[i][d] = base[(size_t)i * QKVC + d];
        ks[i][d] = base[(size_t)i * QKVC + DIMC + d];
        vs[i][d] = base[(size_t)i * QKVC + 2 * DIMC + d];
    }
    const float* mrow = mask + (size_t)(b & (NWIN - 1)) * WIN * WIN;
    for (int idx = tid; idx < WIN * WIN; idx += 256) {
        bi[idx / WIN][idx % WIN] = bias_table[rel_index[idx] * HEADS + h] + mrow[idx];
    }
    __syncthreads();

    const int warp = tid >> 5;
    const int lane = tid & 31;

    for (int r = warp; r < WIN; r += 8) {
        float s0 = 0.f, s1 = 0.f;
        const int j2 = lane + 32;
#pragma unroll
        for (int d = 0; d < HD; d++) {
            float qv = qs[r][d];
            s0 = fmaf(qv, ks[lane][d], s0);
            if (j2 < WIN) s1 = fmaf(qv, ks[j2][d], s1);
        }
        s0 += bi[r][lane];
        s1 = (j2 < WIN) ? (s1 + bi[r][j2]) : -3.0e38f;

        float m = fmaxf(s0, s1);
#pragma unroll
        for (int o = 16; o > 0; o >>= 1)
            m = fmaxf(m, __shfl_xor_sync(0xffffffffu, m, o));

        float e0 = __expf(s0 - m);
        float e1 = (j2 < WIN) ? __expf(s1 - m) : 0.f;
        float sum = e0 + e1;
#pragma unroll
        for (int o = 16; o > 0; o >>= 1)
            sum += __shfl_xor_sync(0xffffffffu, sum, o);

        pr[warp][lane] = e0;
        if (j2 < WIN) pr[warp][j2] = e1;
        __syncwarp();

        const float inv = 1.0f / sum;
        float acc = 0.f;
#pragma unroll
        for (int j = 0; j < WIN; j++)
            acc = fmaf(pr[warp][j], vs[j][lane], acc);

        out[((size_t)b * WIN + r) * DIMC + h * HD + lane] = acc * inv;
        __syncwarp();
    }
}

// ---------------------------------------------------------------------------
extern "C" void kernel_launch(void* const* d_in, const int* in_sizes, int n_in,
                              void* d_out, int out_size) {
    const float* x          = (const float*)d_in[0];
    const float* mask       = (const float*)d_in[1];
    const float* qkv_w      = (const float*)d_in[2];
    const float* qkv_b      = (const float*)d_in[3];
    const float* proj_w     = (const float*)d_in[4];
    const float* proj_b     = (const float*)d_in[5];
    const float* bias_table = (const float*)d_in[6];
    const int*   rel_index  = (const int*)d_in[7];
    float* out = (float*)d_out;

    float *qkv, *att;
    __half *wq_hi, *wq_lo, *wp_hi, *wp_lo;
    cudaGetSymbolAddress((void**)&qkv, g_qkv);
    cudaGetSymbolAddress((void**)&att, g_att);
    cudaGetSymbolAddress((void**)&wq_hi, g_wqkv_hi);
    cudaGetSymbolAddress((void**)&wq_lo, g_wqkv_lo);
    cudaGetSymbolAddress((void**)&wp_hi, g_wprj_hi);
    cudaGetSymbolAddress((void**)&wp_lo, g_wprj_lo);

    cudaFuncSetAttribute(gemm_tc_kernel, cudaFuncAttributeMaxDynamicSharedMemorySize, GEMM_SMEM);

    const float qscale = 0.17677669529663687f; // 32^-0.5

    // 0) weight transpose + fp16 hi/lo split
    prep_w_kernel<<<(KTOT * QKVC + 255) / 256, 256>>>(qkv_w, wq_hi, wq_lo, KTOT, QKVC);
    prep_w_kernel<<<(KTOT * DIMC + 255) / 256, 256>>>(proj_w, wp_hi, wp_lo, KTOT, DIMC);

    // 1) qkv = x @ qkv_w + qkv_b (q columns scaled)
    {
        dim3 grid(QKVC / BN, MROWS / BM);
        gemm_tc_kernel<<<grid, 256, GEMM_SMEM>>>(x, wq_hi, wq_lo, qkv_b, qkv,
                                                 QKVC, DIMC, qscale);
    }
    // 2) fused window attention
    {
        dim3 grid(BATCH, HEADS);
        attn_kernel<<<grid, 256>>>(qkv, mask, bias_table, rel_index, att);
    }
    // 3) out = att @ proj_w + proj_b
    {
        dim3 grid(DIMC / BN, MROWS / BM);
        gemm_tc_kernel<<<grid, 256, GEMM_SMEM>>>(att, wp_hi, wp_lo, proj_b, out,
                                                 DIMC, 0, 1.0f);
    }
}

// round 6
// speedup vs baseline: 1.1341x; 1.1341x over previous
#include <cuda_runtime.h>
#include <cuda_fp16.h>
#include <cstdint>

#define WIN 49
#define HEADS 12
#define HD 32
#define DIMC 384
#define BATCH 4096
#define NWIN 64
#define QKVC (3 * DIMC)     // 1152
#define MROWS (BATCH * WIN) // 200704
#define KTOT 384

// ---------------- scratch (allocation-free rule: __device__ globals) -------
__device__ __half g_qkv[(size_t)MROWS * QKVC]; // [B*49, 1152] fp16, q pre-scaled
__device__ __half g_att[(size_t)MROWS * DIMC]; // [B*49, 384] fp16
__device__ __half g_wqkv_hi[QKVC * KTOT];      // W^T qkv, [N=1152][K=384]
__device__ __half g_wprj_hi[DIMC * KTOT];      // W^T proj, [N=384][K=384]
__device__ __half g_wprj_lo[DIMC * KTOT];

// ---------------- helpers ---------------------------------------------------
__device__ __forceinline__ uint32_t smem_u32(const void* p) {
    uint32_t a;
    asm("{ .reg .u64 t; cvta.to.shared.u64 t, %1; cvt.u32.u64 %0, t; }" : "=r"(a) : "l"(p));
    return a;
}
__device__ __forceinline__ uint32_t pack2_f16(float even, float odd) {
    uint32_t r;
    asm("cvt.rn.f16x2.f32 %0, %1, %2;" : "=r"(r) : "f"(odd), "f"(even));
    return r;
}
__device__ __forceinline__ void ldmx4(uint32_t& r0, uint32_t& r1, uint32_t& r2, uint32_t& r3,
                                      uint32_t addr) {
    asm volatile("ldmatrix.sync.aligned.m8n8.x4.shared.b16 {%0,%1,%2,%3}, [%4];"
                 : "=r"(r0), "=r"(r1), "=r"(r2), "=r"(r3) : "r"(addr));
}
__device__ __forceinline__ void mma16816(float* d, uint32_t a0, uint32_t a1, uint32_t a2,
                                         uint32_t a3, uint32_t b0, uint32_t b1) {
    asm volatile(
        "mma.sync.aligned.m16n8k16.row.col.f32.f16.f16.f32 "
        "{%0,%1,%2,%3}, {%4,%5,%6,%7}, {%8,%9}, {%0,%1,%2,%3};"
        : "+f"(d[0]), "+f"(d[1]), "+f"(d[2]), "+f"(d[3])
        : "r"(a0), "r"(a1), "r"(a2), "r"(a3), "r"(b0), "r"(b1));
}
__device__ __forceinline__ void cp_async16(uint32_t saddr, const void* gaddr) {
    asm volatile("cp.async.cg.shared.global [%0], [%1], 16;" :: "r"(saddr), "l"(gaddr) : "memory");
}

// ---------------------------------------------------------------------------
// Weight prep: W [K][N] fp32 -> Wt_hi (and optional Wt_lo) [N][K] fp16
// ---------------------------------------------------------------------------
__global__ void prep_w_kernel(const float* __restrict__ W,
                              __half* __restrict__ hi,
                              __half* __restrict__ lo, int K, int N, int write_lo) {
    int idx = blockIdx.x * 256 + threadIdx.x;
    if (idx >= K * N) return;
    int k = idx / N, n = idx % N;
    float f = W[idx];
    __half h = __float2half_rn(f);
    hi[(size_t)n * K + k] = h;
    if (write_lo) lo[(size_t)n * K + k] = __float2half_rn(f - __half2float(h));
}

// ---------------------------------------------------------------------------
// Shared tile geometry
// ---------------------------------------------------------------------------
#define BM 128
#define BN 128
#define KC 64
#define NCHUNK (KTOT / KC)  // 6
#define PITCHB 144
#define TILEB (128 * PITCHB)      // 18432

// ---------------------------------------------------------------------------
// qkv GEMM: 1-term fp16. A fp32 -> fp16 in-kernel; C written fp16 (q scaled).
// smem: A tile + Wh tile = 36864 B.
// ---------------------------------------------------------------------------
#define QK_SMEM (2 * TILEB)

__global__ __launch_bounds__(256, 2)
void qkv_gemm_kernel(const float* __restrict__ A,
                     const __half* __restrict__ Bhi,
                     const float* __restrict__ bias, __half* __restrict__ C) {
    extern __shared__ char smem[];
    const uint32_t sb = smem_u32(smem);
    const uint32_t sA = sb, sB = sb + TILEB;
    const int tid = threadIdx.x;
    const int warp = tid >> 5, lane = tid & 31;
    const int wm = warp >> 2, wn = warp & 3;
    const int bm = blockIdx.y * BM, bn = blockIdx.x * BN;

    float acc[4][4][4];
#pragma unroll
    for (int i = 0; i < 4; i++)
#pragma unroll
        for (int j = 0; j < 4; j++)
#pragma unroll
            for (int r = 0; r < 4; r++) acc[i][j][r] = 0.f;

    const float* Abase = A + (size_t)bm * KTOT;

    const int a_r = lane & 15;
    const int a_c = (lane >> 4) * 16;
    const int b_lrow = lane & 7;
    const int b_q = lane >> 3;
    const int b_noff = ((b_q >> 1) * 8) + b_lrow;
    const int b_koff = (b_q & 1) * 16;

    for (int c = 0; c < NCHUNK; c++) {
        const int k0 = c * KC;
        if (c) __syncthreads();

        // Wh tile via cp.async: 1024 granules
#pragma unroll
        for (int i = 0; i < 4; i++) {
            int g = tid + 256 * i;
            int row = g >> 3, k8 = g & 7;
            cp_async16(sB + row * PITCHB + k8 * 16,
                       Bhi + ((size_t)(bn + row) * KTOT + k0 + k8 * 8));
        }
        asm volatile("cp.async.commit_group;" ::: "memory");

        // A tile fp32 -> fp16
#pragma unroll
        for (int i = 0; i < 8; i++) {
            int g = tid + 256 * i;
            int row = g >> 4, k4 = g & 15;
            float4 f = *(const float4*)(Abase + (size_t)row * KTOT + k0 + k4 * 4);
            uint32_t h0 = pack2_f16(f.x, f.y), h1 = pack2_f16(f.z, f.w);
            asm volatile("st.shared.v2.b32 [%0], {%1,%2};"
                         :: "r"(sA + row * PITCHB + k4 * 8), "r"(h0), "r"(h1) : "memory");
        }
        asm volatile("cp.async.wait_group 0;" ::: "memory");
        __syncthreads();

#pragma unroll
        for (int kk = 0; kk < 4; kk++) {
            const uint32_t kbyte = kk * 32;
            uint32_t Ar[4][4], Bh[2][4];
#pragma unroll
            for (int mt = 0; mt < 4; mt++) {
                uint32_t ad = sA + (wm * 64 + mt * 16 + a_r) * PITCHB + kbyte + a_c;
                ldmx4(Ar[mt][0], Ar[mt][1], Ar[mt][2], Ar[mt][3], ad);
            }
#pragma unroll
            for (int p = 0; p < 2; p++) {
                uint32_t bd = sB + (wn * 32 + p * 16 + b_noff) * PITCHB + kbyte + b_koff;
                ldmx4(Bh[p][0], Bh[p][1], Bh[p][2], Bh[p][3], bd);
            }
#pragma unroll
            for (int mt = 0; mt < 4; mt++)
#pragma unroll
                for (int nt = 0; nt < 4; nt++) {
                    const int p = nt >> 1, h = (nt & 1) * 2;
                    mma16816(acc[mt][nt], Ar[mt][0], Ar[mt][1], Ar[mt][2], Ar[mt][3],
                             Bh[p][h], Bh[p][h + 1]);
                }
        }
    }

    // epilogue: bias, q-scale, fp16 store
    const int gid = lane >> 2, tig = lane & 3;
    const float qscale = 0.17677669529663687f;
#pragma unroll
    for (int mt = 0; mt < 4; mt++) {
        const int row = bm + wm * 64 + mt * 16 + gid;
#pragma unroll
        for (int nt = 0; nt < 4; nt++) {
            const int col = bn + wn * 32 + nt * 8 + tig * 2;
            const float b0 = bias[col], b1 = bias[col + 1];
            const float s = (col < DIMC) ? qscale : 1.0f;
            __half2 v0 = __floats2half2_rn((acc[mt][nt][0] + b0) * s, (acc[mt][nt][1] + b1) * s);
            __half2 v1 = __floats2half2_rn((acc[mt][nt][2] + b0) * s, (acc[mt][nt][3] + b1) * s);
            *(__half2*)(C + (size_t)row * QKVC + col) = v0;
            *(__half2*)(C + (size_t)(row + 8) * QKVC + col) = v1;
        }
    }
}

// ---------------------------------------------------------------------------
// proj GEMM: 2-term fp16 (Wh + Wl). A already fp16 (att scratch) via cp.async.
// C fp32 out. smem: A + Wh + Wl = 55296 B.
// ---------------------------------------------------------------------------
#define PJ_SMEM (3 * TILEB)

__global__ __launch_bounds__(256, 2)
void proj_gemm_kernel(const __half* __restrict__ A,
                      const __half* __restrict__ Bhi,
                      const __half* __restrict__ Blo,
                      const float* __restrict__ bias, float* __restrict__ C) {
    extern __shared__ char smem[];
    const uint32_t sb = smem_u32(smem);
    const uint32_t sA = sb, sBH = sb + TILEB, sBL = sb + 2 * TILEB;
    const int tid = threadIdx.x;
    const int warp = tid >> 5, lane = tid & 31;
    const int wm = warp >> 2, wn = warp & 3;
    const int bm = blockIdx.y * BM, bn = blockIdx.x * BN;

    float acc[4][4][4];
#pragma unroll
    for (int i = 0; i < 4; i++)
#pragma unroll
        for (int j = 0; j < 4; j++)
#pragma unroll
            for (int r = 0; r < 4; r++) acc[i][j][r] = 0.f;

    const __half* Abase = A + (size_t)bm * KTOT;

    const int a_r = lane & 15;
    const int a_c = (lane >> 4) * 16;
    const int b_lrow = lane & 7;
    const int b_q = lane >> 3;
    const int b_noff = ((b_q >> 1) * 8) + b_lrow;
    const int b_koff = (b_q & 1) * 16;

    for (int c = 0; c < NCHUNK; c++) {
        const int k0 = c * KC;
        if (c) __syncthreads();

        // A, Wh, Wl tiles via cp.async: 3072 granules
#pragma unroll
        for (int i = 0; i < 12; i++) {
            int g = tid + 256 * i;           // 0..3071
            int sel = g >> 10;               // 0=A, 1=Wh, 2=Wl
            int r = g & 1023;
            int row = r >> 3, k8 = r & 7;
            const __half* src =
                (sel == 0 ? Abase + (size_t)row * KTOT
                 : (sel == 1 ? Bhi : Blo) + (size_t)(bn + row) * KTOT) + k0 + k8 * 8;
            uint32_t dst = (sel == 0 ? sA : (sel == 1 ? sBH : sBL)) + row * PITCHB + k8 * 16;
            cp_async16(dst, src);
        }
        asm volatile("cp.async.commit_group;" ::: "memory");
        asm volatile("cp.async.wait_group 0;" ::: "memory");
        __syncthreads();

#pragma unroll
        for (int kk = 0; kk < 4; kk++) {
            const uint32_t kbyte = kk * 32;
            uint32_t Ar[4][4], Bh[2][4], Bl[2][4];
#pragma unroll
            for (int mt = 0; mt < 4; mt++) {
                uint32_t ad = sA + (wm * 64 + mt * 16 + a_r) * PITCHB + kbyte + a_c;
                ldmx4(Ar[mt][0], Ar[mt][1], Ar[mt][2], Ar[mt][3], ad);
            }
#pragma unroll
            for (int p = 0; p < 2; p++) {
                uint32_t bd = (wn * 32 + p * 16 + b_noff) * PITCHB + kbyte + b_koff;
                ldmx4(Bh[p][0], Bh[p][1], Bh[p][2], Bh[p][3], sBH + bd);
                ldmx4(Bl[p][0], Bl[p][1], Bl[p][2], Bl[p][3], sBL + bd);
            }
#pragma unroll
            for (int mt = 0; mt < 4; mt++)
#pragma unroll
                for (int nt = 0; nt < 4; nt++) {
                    const int p = nt >> 1, h = (nt & 1) * 2;
                    mma16816(acc[mt][nt], Ar[mt][0], Ar[mt][1], Ar[mt][2], Ar[mt][3],
                             Bh[p][h], Bh[p][h + 1]);
                    mma16816(acc[mt][nt], Ar[mt][0], Ar[mt][1], Ar[mt][2], Ar[mt][3],
                             Bl[p][h], Bl[p][h + 1]);
                }
        }
    }

    const int gid = lane >> 2, tig = lane & 3;
#pragma unroll
    for (int mt = 0; mt < 4; mt++) {
        const int row = bm + wm * 64 + mt * 16 + gid;
#pragma unroll
        for (int nt = 0; nt < 4; nt++) {
            const int col = bn + wn * 32 + nt * 8 + tig * 2;
            const float b0 = bias[col], b1 = bias[col + 1];
            float2 v0 = make_float2(acc[mt][nt][0] + b0, acc[mt][nt][1] + b1);
            float2 v1 = make_float2(acc[mt][nt][2] + b0, acc[mt][nt][3] + b1);
            *(float2*)(C + (size_t)row * DIMC + col) = v0;
            *(float2*)(C + (size_t)(row + 8) * DIMC + col) = v1;
        }
    }
}

// ---------------------------------------------------------------------------
// Fused attention per (window b, head h): fp16 in, fp32 math, fp16 out
// ---------------------------------------------------------------------------
__global__ __launch_bounds__(256) void attn_kernel(
    const __half* __restrict__ qkv, const float* __restrict__ mask,
    const float* __restrict__ bias_table, const int* __restrict__ rel_index,
    __half* __restrict__ out) {
    const int b = blockIdx.x;
    const int h = blockIdx.y;

    __shared__ float qs[WIN][HD + 1];
    __shared__ float ks[WIN][HD + 1];
    __shared__ float vs[WIN][HD + 1];
    __shared__ float bi[WIN][WIN];
    __shared__ float pr[8][WIN];

    const int tid = threadIdx.x;
    const __half* base = qkv + (size_t)b * WIN * QKVC + h * HD;

    for (int idx = tid; idx < WIN * HD / 2; idx += 256) {
        int i = idx >> 4, d2 = idx & 15;            // half2 granule
        float2 q2 = __half22float2(*(const __half2*)(base + (size_t)i * QKVC + d2 * 2));
        float2 k2 = __half22float2(*(const __half2*)(base + (size_t)i * QKVC + DIMC + d2 * 2));
        float2 v2 = __half22float2(*(const __half2*)(base + (size_t)i * QKVC + 2 * DIMC + d2 * 2));
        qs[i][d2 * 2] = q2.x; qs[i][d2 * 2 + 1] = q2.y;
        ks[i][d2 * 2] = k2.x; ks[i][d2 * 2 + 1] = k2.y;
        vs[i][d2 * 2] = v2.x; vs[i][d2 * 2 + 1] = v2.y;
    }
    const float* mrow = mask + (size_t)(b & (NWIN - 1)) * WIN * WIN;
    for (int idx = tid; idx < WIN * WIN; idx += 256) {
        bi[idx / WIN][idx % WIN] = bias_table[rel_index[idx] * HEADS + h] + mrow[idx];
    }
    __syncthreads();

    const int warp = tid >> 5;
    const int lane = tid & 31;

    for (int r = warp; r < WIN; r += 8) {
        float s0 = 0.f, s1 = 0.f;
        const int j2 = lane + 32;
#pragma unroll
        for (int d = 0; d < HD; d++) {
            float qv = qs[r][d];
            s0 = fmaf(qv, ks[lane][d], s0);
            if (j2 < WIN) s1 = fmaf(qv, ks[j2][d], s1);
        }
        s0 += bi[r][lane];
        s1 = (j2 < WIN) ? (s1 + bi[r][j2]) : -3.0e38f;

        float m = fmaxf(s0, s1);
#pragma unroll
        for (int o = 16; o > 0; o >>= 1)
            m = fmaxf(m, __shfl_xor_sync(0xffffffffu, m, o));

        float e0 = __expf(s0 - m);
        float e1 = (j2 < WIN) ? __expf(s1 - m) : 0.f;
        float sum = e0 + e1;
#pragma unroll
        for (int o = 16; o > 0; o >>= 1)
            sum += __shfl_xor_sync(0xffffffffu, sum, o);

        pr[warp][lane] = e0;
        if (j2 < WIN) pr[warp][j2] = e1;
        __syncwarp();

        const float inv = 1.0f / sum;
        float acc = 0.f;
#pragma unroll
        for (int j = 0; j < WIN; j++)
            acc = fmaf(pr[warp][j], vs[j][lane], acc);

        out[((size_t)b * WIN + r) * DIMC + h * HD + lane] = __float2half_rn(acc * inv);
        __syncwarp();
    }
}

// ---------------------------------------------------------------------------
extern "C" void kernel_launch(void* const* d_in, const int* in_sizes, int n_in,
                              void* d_out, int out_size) {
    const float* x          = (const float*)d_in[0];
    const float* mask       = (const float*)d_in[1];
    const float* qkv_w      = (const float*)d_in[2];
    const float* qkv_b      = (const float*)d_in[3];
    const float* proj_w     = (const float*)d_in[4];
    const float* proj_b     = (const float*)d_in[5];
    const float* bias_table = (const float*)d_in[6];
    const int*   rel_index  = (const int*)d_in[7];
    float* out = (float*)d_out;

    __half *qkv, *att, *wq_hi, *wp_hi, *wp_lo;
    cudaGetSymbolAddress((void**)&qkv, g_qkv);
    cudaGetSymbolAddress((void**)&att, g_att);
    cudaGetSymbolAddress((void**)&wq_hi, g_wqkv_hi);
    cudaGetSymbolAddress((void**)&wp_hi, g_wprj_hi);
    cudaGetSymbolAddress((void**)&wp_lo, g_wprj_lo);

    cudaFuncSetAttribute(qkv_gemm_kernel, cudaFuncAttributeMaxDynamicSharedMemorySize, QK_SMEM);
    cudaFuncSetAttribute(proj_gemm_kernel, cudaFuncAttributeMaxDynamicSharedMemorySize, PJ_SMEM);

    // 0) weight transpose + fp16 split
    prep_w_kernel<<<(KTOT * QKVC + 255) / 256, 256>>>(qkv_w, wq_hi, nullptr, KTOT, QKVC, 0);
    prep_w_kernel<<<(KTOT * DIMC + 255) / 256, 256>>>(proj_w, wp_hi, wp_lo, KTOT, DIMC, 1);

    // 1) qkv = x @ qkv_w + qkv_b (q columns scaled), fp16 out
    {
        dim3 grid(QKVC / BN, MROWS / BM);
        qkv_gemm_kernel<<<grid, 256, QK_SMEM>>>(x, wq_hi, qkv_b, qkv);
    }
    // 2) fused window attention (fp16 in/out)
    {
        dim3 grid(BATCH, HEADS);
        attn_kernel<<<grid, 256>>>(qkv, mask, bias_table, rel_index, att);
    }
    // 3) out = att @ proj_w + proj_b (fp32 out)
    {
        dim3 grid(DIMC / BN, MROWS / BM);
        proj_gemm_kernel<<<grid, 256, PJ_SMEM>>>(att, wp_hi, wp_lo, proj_b, out);
    }
}

// round 7
// speedup vs baseline: 1.1656x; 1.0278x over previous
#include <cuda_runtime.h>
#include <cuda_fp16.h>
#include <cstdint>

#define WIN 49
#define HEADS 12
#define HD 32
#define DIMC 384
#define BATCH 4096
#define NWIN 64
#define QKVC (3 * DIMC)     // 1152
#define MROWS (BATCH * WIN) // 200704
#define KTOT 384

// ---------------- scratch (allocation-free rule: __device__ globals) -------
__device__ __half g_x16[(size_t)MROWS * KTOT];  // x rounded to fp16
__device__ __half g_qkv[(size_t)MROWS * QKVC];  // [B*49, 1152] fp16, q pre-scaled
__device__ __half g_att[(size_t)MROWS * DIMC];  // [B*49, 384] fp16
__device__ __half g_wqkv_hi[QKVC * KTOT];       // W^T qkv, [N=1152][K=384]
__device__ __half g_wprj_hi[DIMC * KTOT];       // W^T proj, [N=384][K=384]
__device__ __half g_wprj_lo[DIMC * KTOT];

// ---------------- helpers ---------------------------------------------------
__device__ __forceinline__ uint32_t smem_u32(const void* p) {
    uint32_t a;
    asm("{ .reg .u64 t; cvta.to.shared.u64 t, %1; cvt.u32.u64 %0, t; }" : "=r"(a) : "l"(p));
    return a;
}
__device__ __forceinline__ uint32_t pack2_f16(float even, float odd) {
    uint32_t r;
    asm("cvt.rn.f16x2.f32 %0, %1, %2;" : "=r"(r) : "f"(odd), "f"(even));
    return r;
}
__device__ __forceinline__ void ldmx4(uint32_t& r0, uint32_t& r1, uint32_t& r2, uint32_t& r3,
                                      uint32_t addr) {
    asm volatile("ldmatrix.sync.aligned.m8n8.x4.shared.b16 {%0,%1,%2,%3}, [%4];"
                 : "=r"(r0), "=r"(r1), "=r"(r2), "=r"(r3) : "r"(addr));
}
__device__ __forceinline__ void mma16816(float* d, uint32_t a0, uint32_t a1, uint32_t a2,
                                         uint32_t a3, uint32_t b0, uint32_t b1) {
    asm volatile(
        "mma.sync.aligned.m16n8k16.row.col.f32.f16.f16.f32 "
        "{%0,%1,%2,%3}, {%4,%5,%6,%7}, {%8,%9}, {%0,%1,%2,%3};"
        : "+f"(d[0]), "+f"(d[1]), "+f"(d[2]), "+f"(d[3])
        : "r"(a0), "r"(a1), "r"(a2), "r"(a3), "r"(b0), "r"(b1));
}
__device__ __forceinline__ void cp_async16(uint32_t saddr, const void* gaddr) {
    asm volatile("cp.async.cg.shared.global [%0], [%1], 16;" :: "r"(saddr), "l"(gaddr) : "memory");
}

// ---------------------------------------------------------------------------
// prep_x: x fp32 -> fp16 (one pass; identical rounding to prior in-GEMM cvt)
// ---------------------------------------------------------------------------
__global__ void prep_x_kernel(const float* __restrict__ X, __half* __restrict__ Y) {
    size_t idx = (size_t)blockIdx.x * 256 + threadIdx.x;   // one float4 per thread
    float4 f = *(const float4*)(X + idx * 4);
    uint32_t h0 = pack2_f16(f.x, f.y), h1 = pack2_f16(f.z, f.w);
    *(uint2*)(Y + idx * 4) = make_uint2(h0, h1);
}

// ---------------------------------------------------------------------------
// Weight prep: W [K][N] fp32 -> Wt_hi (and optional Wt_lo) [N][K] fp16
// ---------------------------------------------------------------------------
__global__ void prep_w_kernel(const float* __restrict__ W,
                              __half* __restrict__ hi,
                              __half* __restrict__ lo, int K, int N, int write_lo) {
    int idx = blockIdx.x * 256 + threadIdx.x;
    if (idx >= K * N) return;
    int k = idx / N, n = idx % N;
    float f = W[idx];
    __half h = __float2half_rn(f);
    hi[(size_t)n * K + k] = h;
    if (write_lo) lo[(size_t)n * K + k] = __float2half_rn(f - __half2float(h));
}

// ---------------------------------------------------------------------------
// Tile geometry
// ---------------------------------------------------------------------------
#define BM 128
#define BN 128
#define KC 64
#define NCHUNK (KTOT / KC)  // 6
#define PITCHB 144
#define TILEB (128 * PITCHB)      // 18432

// ---------------------------------------------------------------------------
// qkv GEMM: 1-term fp16, double-buffered cp.async. A fp16, C fp16 (q scaled).
// stage = A + Wh = 36864 B; 2 stages = 73728 B.
// ---------------------------------------------------------------------------
#define QK_STAGE (2 * TILEB)
#define QK_SMEM (2 * QK_STAGE)

__global__ __launch_bounds__(256, 2)
void qkv_gemm_kernel(const __half* __restrict__ A,
                     const __half* __restrict__ Bhi,
                     const float* __restrict__ bias, __half* __restrict__ C) {
    extern __shared__ char smem[];
    const uint32_t sb = smem_u32(smem);
    const int tid = threadIdx.x;
    const int warp = tid >> 5, lane = tid & 31;
    const int wm = warp >> 2, wn = warp & 3;
    const int bm = blockIdx.y * BM, bn = blockIdx.x * BN;

    float acc[4][4][4];
#pragma unroll
    for (int i = 0; i < 4; i++)
#pragma unroll
        for (int j = 0; j < 4; j++)
#pragma unroll
            for (int r = 0; r < 4; r++) acc[i][j][r] = 0.f;

    const __half* Abase = A + (size_t)bm * KTOT;

    const int a_r = lane & 15;
    const int a_c = (lane >> 4) * 16;
    const int b_lrow = lane & 7;
    const int b_q = lane >> 3;
    const int b_noff = ((b_q >> 1) * 8) + b_lrow;
    const int b_koff = (b_q & 1) * 16;

    // loader geometry: 2048 granules; g = tid + 256*i, i<8
    //   sel = g>>10 (0=A, 1=Wh); r = g&1023; row=r>>3; k8=r&7
#define QK_ISSUE(stg, k0)                                                        \
    do {                                                                         \
        _Pragma("unroll")                                                        \
        for (int i = 0; i < 8; i++) {                                            \
            int g = tid + 256 * i;                                               \
            int sel = g >> 10;                                                   \
            int r = g & 1023;                                                    \
            int row = r >> 3, k8 = r & 7;                                        \
            const __half* src = (sel ? Bhi + (size_t)(bn + row) * KTOT           \
                                     : Abase + (size_t)row * KTOT) + (k0) + k8 * 8; \
            cp_async16((stg) + sel * TILEB + row * PITCHB + k8 * 16, src);       \
        }                                                                        \
        asm volatile("cp.async.commit_group;" ::: "memory");                     \
    } while (0)

    QK_ISSUE(sb, 0);

    for (int c = 0; c < NCHUNK; c++) {
        const uint32_t sp = sb + (uint32_t)(c & 1) * QK_STAGE;
        const bool pf = (c + 1 < NCHUNK);
        if (pf) QK_ISSUE(sb + (uint32_t)((c + 1) & 1) * QK_STAGE, (c + 1) * KC);
        if (pf) { asm volatile("cp.async.wait_group 1;" ::: "memory"); }
        else    { asm volatile("cp.async.wait_group 0;" ::: "memory"); }
        __syncthreads();

#pragma unroll
        for (int kk = 0; kk < 4; kk++) {
            const uint32_t kbyte = kk * 32;
            uint32_t Ar[4][4], Bh[2][4];
#pragma unroll
            for (int mt = 0; mt < 4; mt++) {
                uint32_t ad = sp + (wm * 64 + mt * 16 + a_r) * PITCHB + kbyte + a_c;
                ldmx4(Ar[mt][0], Ar[mt][1], Ar[mt][2], Ar[mt][3], ad);
            }
#pragma unroll
            for (int p = 0; p < 2; p++) {
                uint32_t bd = sp + TILEB + (wn * 32 + p * 16 + b_noff) * PITCHB + kbyte + b_koff;
                ldmx4(Bh[p][0], Bh[p][1], Bh[p][2], Bh[p][3], bd);
            }
#pragma unroll
            for (int mt = 0; mt < 4; mt++)
#pragma unroll
                for (int nt = 0; nt < 4; nt++) {
                    const int p = nt >> 1, h = (nt & 1) * 2;
                    mma16816(acc[mt][nt], Ar[mt][0], Ar[mt][1], Ar[mt][2], Ar[mt][3],
                             Bh[p][h], Bh[p][h + 1]);
                }
        }
        __syncthreads();   // protect stage about to be overwritten next iter
    }

    const int gid = lane >> 2, tig = lane & 3;
    const float qscale = 0.17677669529663687f;
#pragma unroll
    for (int mt = 0; mt < 4; mt++) {
        const int row = bm + wm * 64 + mt * 16 + gid;
#pragma unroll
        for (int nt = 0; nt < 4; nt++) {
            const int col = bn + wn * 32 + nt * 8 + tig * 2;
            const float b0 = bias[col], b1 = bias[col + 1];
            const float s = (col < DIMC) ? qscale : 1.0f;
            __half2 v0 = __floats2half2_rn((acc[mt][nt][0] + b0) * s, (acc[mt][nt][1] + b1) * s);
            __half2 v1 = __floats2half2_rn((acc[mt][nt][2] + b0) * s, (acc[mt][nt][3] + b1) * s);
            *(__half2*)(C + (size_t)row * QKVC + col) = v0;
            *(__half2*)(C + (size_t)(row + 8) * QKVC + col) = v1;
        }
    }
#undef QK_ISSUE
}

// ---------------------------------------------------------------------------
// proj GEMM: 2-term fp16 (Wh+Wl), double-buffered cp.async. A fp16, C fp32.
// stage = A + Wh + Wl = 55296 B; 2 stages = 110592 B.
// ---------------------------------------------------------------------------
#define PJ_STAGE (3 * TILEB)
#define PJ_SMEM (2 * PJ_STAGE)

__global__ __launch_bounds__(256, 2)
void proj_gemm_kernel(const __half* __restrict__ A,
                      const __half* __restrict__ Bhi,
                      const __half* __restrict__ Blo,
                      const float* __restrict__ bias, float* __restrict__ C) {
    extern __shared__ char smem[];
    const uint32_t sb = smem_u32(smem);
    const int tid = threadIdx.x;
    const int warp = tid >> 5, lane = tid & 31;
    const int wm = warp >> 2, wn = warp & 3;
    const int bm = blockIdx.y * BM, bn = blockIdx.x * BN;

    float acc[4][4][4];
#pragma unroll
    for (int i = 0; i < 4; i++)
#pragma unroll
        for (int j = 0; j < 4; j++)
#pragma unroll
            for (int r = 0; r < 4; r++) acc[i][j][r] = 0.f;

    const __half* Abase = A + (size_t)bm * KTOT;

    const int a_r = lane & 15;
    const int a_c = (lane >> 4) * 16;
    const int b_lrow = lane & 7;
    const int b_q = lane >> 3;
    const int b_noff = ((b_q >> 1) * 8) + b_lrow;
    const int b_koff = (b_q & 1) * 16;

#define PJ_ISSUE(stg, k0)                                                        \
    do {                                                                         \
        _Pragma("unroll")                                                        \
        for (int i = 0; i < 12; i++) {                                           \
            int g = tid + 256 * i;                                               \
            int sel = g >> 10;                                                   \
            int r = g & 1023;                                                    \
            int row = r >> 3, k8 = r & 7;                                        \
            const __half* src =                                                  \
                (sel == 0 ? Abase + (size_t)row * KTOT                           \
                          : (sel == 1 ? Bhi : Blo) + (size_t)(bn + row) * KTOT)  \
                + (k0) + k8 * 8;                                                 \
            cp_async16((stg) + sel * TILEB + row * PITCHB + k8 * 16, src);       \
        }                                                                        \
        asm volatile("cp.async.commit_group;" ::: "memory");                     \
    } while (0)

    PJ_ISSUE(sb, 0);

    for (int c = 0; c < NCHUNK; c++) {
        const uint32_t sp = sb + (uint32_t)(c & 1) * PJ_STAGE;
        const bool pf = (c + 1 < NCHUNK);
        if (pf) PJ_ISSUE(sb + (uint32_t)((c + 1) & 1) * PJ_STAGE, (c + 1) * KC);
        if (pf) { asm volatile("cp.async.wait_group 1;" ::: "memory"); }
        else    { asm volatile("cp.async.wait_group 0;" ::: "memory"); }
        __syncthreads();

#pragma unroll
        for (int kk = 0; kk < 4; kk++) {
            const uint32_t kbyte = kk * 32;
            uint32_t Ar[4][4], Bh[2][4], Bl[2][4];
#pragma unroll
            for (int mt = 0; mt < 4; mt++) {
                uint32_t ad = sp + (wm * 64 + mt * 16 + a_r) * PITCHB + kbyte + a_c;
                ldmx4(Ar[mt][0], Ar[mt][1], Ar[mt][2], Ar[mt][3], ad);
            }
#pragma unroll
            for (int p = 0; p < 2; p++) {
                uint32_t bd = (wn * 32 + p * 16 + b_noff) * PITCHB + kbyte + b_koff;
                ldmx4(Bh[p][0], Bh[p][1], Bh[p][2], Bh[p][3], sp + TILEB + bd);
                ldmx4(Bl[p][0], Bl[p][1], Bl[p][2], Bl[p][3], sp + 2 * TILEB + bd);
            }
#pragma unroll
            for (int mt = 0; mt < 4; mt++)
#pragma unroll
                for (int nt = 0; nt < 4; nt++) {
                    const int p = nt >> 1, h = (nt & 1) * 2;
                    mma16816(acc[mt][nt], Ar[mt][0], Ar[mt][1], Ar[mt][2], Ar[mt][3],
                             Bh[p][h], Bh[p][h + 1]);
                    mma16816(acc[mt][nt], Ar[mt][0], Ar[mt][1], Ar[mt][2], Ar[mt][3],
                             Bl[p][h], Bl[p][h + 1]);
                }
        }
        __syncthreads();
    }

    const int gid = lane >> 2, tig = lane & 3;
#pragma unroll
    for (int mt = 0; mt < 4; mt++) {
        const int row = bm + wm * 64 + mt * 16 + gid;
#pragma unroll
        for (int nt = 0; nt < 4; nt++) {
            const int col = bn + wn * 32 + nt * 8 + tig * 2;
            const float b0 = bias[col], b1 = bias[col + 1];
            float2 v0 = make_float2(acc[mt][nt][0] + b0, acc[mt][nt][1] + b1);
            float2 v1 = make_float2(acc[mt][nt][2] + b0, acc[mt][nt][3] + b1);
            *(float2*)(C + (size_t)row * DIMC + col) = v0;
            *(float2*)(C + (size_t)(row + 8) * DIMC + col) = v1;
        }
    }
#undef PJ_ISSUE
}

// ---------------------------------------------------------------------------
// Fused attention per (window b, head h): fp16 in, fp32 math, fp16 out
// ---------------------------------------------------------------------------
__global__ __launch_bounds__(256) void attn_kernel(
    const __half* __restrict__ qkv, const float* __restrict__ mask,
    const float* __restrict__ bias_table, const int* __restrict__ rel_index,
    __half* __restrict__ out) {
    const int b = blockIdx.x;
    const int h = blockIdx.y;

    __shared__ float qs[WIN][HD + 1];
    __shared__ float ks[WIN][HD + 1];
    __shared__ float vs[WIN][HD + 1];
    __shared__ float bi[WIN][WIN];
    __shared__ float pr[8][WIN];

    const int tid = threadIdx.x;
    const __half* base = qkv + (size_t)b * WIN * QKVC + h * HD;

    for (int idx = tid; idx < WIN * HD / 2; idx += 256) {
        int i = idx >> 4, d2 = idx & 15;
        float2 q2 = __half22float2(*(const __half2*)(base + (size_t)i * QKVC + d2 * 2));
        float2 k2 = __half22float2(*(const __half2*)(base + (size_t)i * QKVC + DIMC + d2 * 2));
        float2 v2 = __half22float2(*(const __half2*)(base + (size_t)i * QKVC + 2 * DIMC + d2 * 2));
        qs[i][d2 * 2] = q2.x; qs[i][d2 * 2 + 1] = q2.y;
        ks[i][d2 * 2] = k2.x; ks[i][d2 * 2 + 1] = k2.y;
        vs[i][d2 * 2] = v2.x; vs[i][d2 * 2 + 1] = v2.y;
    }
    const float* mrow = mask + (size_t)(b & (NWIN - 1)) * WIN * WIN;
    for (int idx = tid; idx < WIN * WIN; idx += 256) {
        bi[idx / WIN][idx % WIN] = bias_table[rel_index[idx] * HEADS + h] + mrow[idx];
    }
    __syncthreads();

    const int warp = tid >> 5;
    const int lane = tid & 31;

    for (int r = warp; r < WIN; r += 8) {
        float s0 = 0.f, s1 = 0.f;
        const int j2 = lane + 32;
#pragma unroll
        for (int d = 0; d < HD; d++) {
            float qv = qs[r][d];
            s0 = fmaf(qv, ks[lane][d], s0);
            if (j2 < WIN) s1 = fmaf(qv, ks[j2][d], s1);
        }
        s0 += bi[r][lane];
        s1 = (j2 < WIN) ? (s1 + bi[r][j2]) : -3.0e38f;

        float m = fmaxf(s0, s1);
#pragma unroll
        for (int o = 16; o > 0; o >>= 1)
            m = fmaxf(m, __shfl_xor_sync(0xffffffffu, m, o));

        float e0 = __expf(s0 - m);
        float e1 = (j2 < WIN) ? __expf(s1 - m) : 0.f;
        float sum = e0 + e1;
#pragma unroll
        for (int o = 16; o > 0; o >>= 1)
            sum += __shfl_xor_sync(0xffffffffu, sum, o);

        pr[warp][lane] = e0;
        if (j2 < WIN) pr[warp][j2] = e1;
        __syncwarp();

        const float inv = 1.0f / sum;
        float acc = 0.f;
#pragma unroll
        for (int j = 0; j < WIN; j++)
            acc = fmaf(pr[warp][j], vs[j][lane], acc);

        out[((size_t)b * WIN + r) * DIMC + h * HD + lane] = __float2half_rn(acc * inv);
        __syncwarp();
    }
}

// ---------------------------------------------------------------------------
extern "C" void kernel_launch(void* const* d_in, const int* in_sizes, int n_in,
                              void* d_out, int out_size) {
    const float* x          = (const float*)d_in[0];
    const float* mask       = (const float*)d_in[1];
    const float* qkv_w      = (const float*)d_in[2];
    const float* qkv_b      = (const float*)d_in[3];
    const float* proj_w     = (const float*)d_in[4];
    const float* proj_b     = (const float*)d_in[5];
    const float* bias_table = (const float*)d_in[6];
    const int*   rel_index  = (const int*)d_in[7];
    float* out = (float*)d_out;

    __half *x16, *qkv, *att, *wq_hi, *wp_hi, *wp_lo;
    cudaGetSymbolAddress((void**)&x16, g_x16);
    cudaGetSymbolAddress((void**)&qkv, g_qkv);
    cudaGetSymbolAddress((void**)&att, g_att);
    cudaGetSymbolAddress((void**)&wq_hi, g_wqkv_hi);
    cudaGetSymbolAddress((void**)&wp_hi, g_wprj_hi);
    cudaGetSymbolAddress((void**)&wp_lo, g_wprj_lo);

    cudaFuncSetAttribute(qkv_gemm_kernel, cudaFuncAttributeMaxDynamicSharedMemorySize, QK_SMEM);
    cudaFuncSetAttribute(proj_gemm_kernel, cudaFuncAttributeMaxDynamicSharedMemorySize, PJ_SMEM);

    // 0) x -> fp16, weight transpose + fp16 split
    prep_x_kernel<<<(size_t)MROWS * KTOT / 4 / 256, 256>>>(x, x16);
    prep_w_kernel<<<(KTOT * QKVC + 255) / 256, 256>>>(qkv_w, wq_hi, nullptr, KTOT, QKVC, 0);
    prep_w_kernel<<<(KTOT * DIMC + 255) / 256, 256>>>(proj_w, wp_hi, wp_lo, KTOT, DIMC, 1);

    // 1) qkv = x16 @ qkv_w + qkv_b (q columns scaled), fp16 out
    {
        dim3 grid(QKVC / BN, MROWS / BM);
        qkv_gemm_kernel<<<grid, 256, QK_SMEM>>>(x16, wq_hi, qkv_b, qkv);
    }
    // 2) fused window attention (fp16 in/out)
    {
        dim3 grid(BATCH, HEADS);
        attn_kernel<<<grid, 256>>>(qkv, mask, bias_table, rel_index, att);
    }
    // 3) out = att @ proj_w + proj_b (fp32 out)
    {
        dim3 grid(DIMC / BN, MROWS / BM);
        proj_gemm_kernel<<<grid, 256, PJ_SMEM>>>(att, wp_hi, wp_lo, proj_b, out);
    }
}

// round 8
// speedup vs baseline: 1.6358x; 1.4034x over previous
#include <cuda_runtime.h>
#include <cuda_fp16.h>
#include <cstdint>

#define WIN 49
#define HEADS 12
#define HD 32
#define DIMC 384
#define BATCH 4096
#define NWIN 64
#define QKVC (3 * DIMC)     // 1152
#define MROWS (BATCH * WIN) // 200704
#define KTOT 384

// ---------------- scratch (allocation-free rule: __device__ globals) -------
__device__ __half g_x16[(size_t)MROWS * KTOT];
__device__ __half g_qkv[(size_t)MROWS * QKVC];
__device__ __half g_att[(size_t)MROWS * DIMC];
__device__ __half g_wqkv_hi[QKVC * KTOT];
__device__ __half g_wprj_hi[DIMC * KTOT];
__device__ __half g_wprj_lo[DIMC * KTOT];
__device__ float  g_bm[(size_t)NWIN * HEADS * WIN * WIN]; // mask+bias combined

// ---------------- helpers ---------------------------------------------------
__device__ __forceinline__ uint32_t smem_u32(const void* p) {
    uint32_t a;
    asm("{ .reg .u64 t; cvta.to.shared.u64 t, %1; cvt.u32.u64 %0, t; }" : "=r"(a) : "l"(p));
    return a;
}
__device__ __forceinline__ uint32_t pack2_f16(float even, float odd) {
    uint32_t r;
    asm("cvt.rn.f16x2.f32 %0, %1, %2;" : "=r"(r) : "f"(odd), "f"(even));
    return r;
}
__device__ __forceinline__ void ldmx4(uint32_t& r0, uint32_t& r1, uint32_t& r2, uint32_t& r3,
                                      uint32_t addr) {
    asm volatile("ldmatrix.sync.aligned.m8n8.x4.shared.b16 {%0,%1,%2,%3}, [%4];"
                 : "=r"(r0), "=r"(r1), "=r"(r2), "=r"(r3) : "r"(addr));
}
__device__ __forceinline__ void ldmx4t(uint32_t& r0, uint32_t& r1, uint32_t& r2, uint32_t& r3,
                                       uint32_t addr) {
    asm volatile("ldmatrix.sync.aligned.m8n8.x4.trans.shared.b16 {%0,%1,%2,%3}, [%4];"
                 : "=r"(r0), "=r"(r1), "=r"(r2), "=r"(r3) : "r"(addr));
}
__device__ __forceinline__ void mma16816(float* d, uint32_t a0, uint32_t a1, uint32_t a2,
                                         uint32_t a3, uint32_t b0, uint32_t b1) {
    asm volatile(
        "mma.sync.aligned.m16n8k16.row.col.f32.f16.f16.f32 "
        "{%0,%1,%2,%3}, {%4,%5,%6,%7}, {%8,%9}, {%0,%1,%2,%3};"
        : "+f"(d[0]), "+f"(d[1]), "+f"(d[2]), "+f"(d[3])
        : "r"(a0), "r"(a1), "r"(a2), "r"(a3), "r"(b0), "r"(b1));
}
__device__ __forceinline__ void cp_async16(uint32_t saddr, const void* gaddr) {
    asm volatile("cp.async.cg.shared.global [%0], [%1], 16;" :: "r"(saddr), "l"(gaddr) : "memory");
}

// ---------------------------------------------------------------------------
// prep kernels
// ---------------------------------------------------------------------------
__global__ void prep_x_kernel(const float* __restrict__ X, __half* __restrict__ Y) {
    size_t idx = (size_t)blockIdx.x * 256 + threadIdx.x;
    float4 f = *(const float4*)(X + idx * 4);
    uint32_t h0 = pack2_f16(f.x, f.y), h1 = pack2_f16(f.z, f.w);
    *(uint2*)(Y + idx * 4) = make_uint2(h0, h1);
}

__global__ void prep_w_kernel(const float* __restrict__ W,
                              __half* __restrict__ hi,
                              __half* __restrict__ lo, int K, int N, int write_lo) {
    int idx = blockIdx.x * 256 + threadIdx.x;
    if (idx >= K * N) return;
    int k = idx / N, n = idx % N;
    float f = W[idx];
    __half h = __float2half_rn(f);
    hi[(size_t)n * K + k] = h;
    if (write_lo) lo[(size_t)n * K + k] = __float2half_rn(f - __half2float(h));
}

// combined[nw][h][r*49+c] = mask[nw][r][c] + bias_table[rel_index[r*49+c]][h]
__global__ void prep_bm_kernel(const float* __restrict__ mask,
                               const float* __restrict__ bias_table,
                               const int* __restrict__ rel_index,
                               float* __restrict__ bm) {
    int idx = blockIdx.x * 256 + threadIdx.x;
    if (idx >= NWIN * HEADS * WIN * WIN) return;
    int rc = idx % (WIN * WIN);
    int nwh = idx / (WIN * WIN);
    int h = nwh % HEADS, nw = nwh / HEADS;
    bm[idx] = mask[nw * WIN * WIN + rc] + bias_table[rel_index[rc] * HEADS + h];
}

// ---------------------------------------------------------------------------
// Tile geometry (GEMMs)
// ---------------------------------------------------------------------------
#define BM 128
#define BN 128
#define KC 64
#define NCHUNK (KTOT / KC)
#define PITCHB 144
#define TILEB (128 * PITCHB)

// ---------------------------------------------------------------------------
// qkv GEMM: 1-term fp16, double-buffered cp.async (unchanged from R7)
// ---------------------------------------------------------------------------
#define QK_STAGE (2 * TILEB)
#define QK_SMEM (2 * QK_STAGE)

__global__ __launch_bounds__(256, 2)
void qkv_gemm_kernel(const __half* __restrict__ A,
                     const __half* __restrict__ Bhi,
                     const float* __restrict__ bias, __half* __restrict__ C) {
    extern __shared__ char smem[];
    const uint32_t sb = smem_u32(smem);
    const int tid = threadIdx.x;
    const int warp = tid >> 5, lane = tid & 31;
    const int wm = warp >> 2, wn = warp & 3;
    const int bm = blockIdx.y * BM, bn = blockIdx.x * BN;

    float acc[4][4][4];
#pragma unroll
    for (int i = 0; i < 4; i++)
#pragma unroll
        for (int j = 0; j < 4; j++)
#pragma unroll
            for (int r = 0; r < 4; r++) acc[i][j][r] = 0.f;

    const __half* Abase = A + (size_t)bm * KTOT;
    const int a_r = lane & 15;
    const int a_c = (lane >> 4) * 16;
    const int b_lrow = lane & 7;
    const int b_q = lane >> 3;
    const int b_noff = ((b_q >> 1) * 8) + b_lrow;
    const int b_koff = (b_q & 1) * 16;

#define QK_ISSUE(stg, k0)                                                        \
    do {                                                                         \
        _Pragma("unroll")                                                        \
        for (int i = 0; i < 8; i++) {                                            \
            int g = tid + 256 * i;                                               \
            int sel = g >> 10;                                                   \
            int r = g & 1023;                                                    \
            int row = r >> 3, k8 = r & 7;                                        \
            const __half* src = (sel ? Bhi + (size_t)(bn + row) * KTOT           \
                                     : Abase + (size_t)row * KTOT) + (k0) + k8 * 8; \
            cp_async16((stg) + sel * TILEB + row * PITCHB + k8 * 16, src);       \
        }                                                                        \
        asm volatile("cp.async.commit_group;" ::: "memory");                     \
    } while (0)

    QK_ISSUE(sb, 0);

    for (int c = 0; c < NCHUNK; c++) {
        const uint32_t sp = sb + (uint32_t)(c & 1) * QK_STAGE;
        const bool pf = (c + 1 < NCHUNK);
        if (pf) QK_ISSUE(sb + (uint32_t)((c + 1) & 1) * QK_STAGE, (c + 1) * KC);
        if (pf) { asm volatile("cp.async.wait_group 1;" ::: "memory"); }
        else    { asm volatile("cp.async.wait_group 0;" ::: "memory"); }
        __syncthreads();

#pragma unroll
        for (int kk = 0; kk < 4; kk++) {
            const uint32_t kbyte = kk * 32;
            uint32_t Ar[4][4], Bh[2][4];
#pragma unroll
            for (int mt = 0; mt < 4; mt++)
                ldmx4(Ar[mt][0], Ar[mt][1], Ar[mt][2], Ar[mt][3],
                      sp + (wm * 64 + mt * 16 + a_r) * PITCHB + kbyte + a_c);
#pragma unroll
            for (int p = 0; p < 2; p++)
                ldmx4(Bh[p][0], Bh[p][1], Bh[p][2], Bh[p][3],
                      sp + TILEB + (wn * 32 + p * 16 + b_noff) * PITCHB + kbyte + b_koff);
#pragma unroll
            for (int mt = 0; mt < 4; mt++)
#pragma unroll
                for (int nt = 0; nt < 4; nt++) {
                    const int p = nt >> 1, h = (nt & 1) * 2;
                    mma16816(acc[mt][nt], Ar[mt][0], Ar[mt][1], Ar[mt][2], Ar[mt][3],
                             Bh[p][h], Bh[p][h + 1]);
                }
        }
        __syncthreads();
    }

    const int gid = lane >> 2, tig = lane & 3;
    const float qscale = 0.17677669529663687f;
#pragma unroll
    for (int mt = 0; mt < 4; mt++) {
        const int row = bm + wm * 64 + mt * 16 + gid;
#pragma unroll
        for (int nt = 0; nt < 4; nt++) {
            const int col = bn + wn * 32 + nt * 8 + tig * 2;
            const float b0 = bias[col], b1 = bias[col + 1];
            const float s = (col < DIMC) ? qscale : 1.0f;
            __half2 v0 = __floats2half2_rn((acc[mt][nt][0] + b0) * s, (acc[mt][nt][1] + b1) * s);
            __half2 v1 = __floats2half2_rn((acc[mt][nt][2] + b0) * s, (acc[mt][nt][3] + b1) * s);
            *(__half2*)(C + (size_t)row * QKVC + col) = v0;
            *(__half2*)(C + (size_t)(row + 8) * QKVC + col) = v1;
        }
    }
#undef QK_ISSUE
}

// ---------------------------------------------------------------------------
// proj GEMM: 2-term fp16, double-buffered cp.async (unchanged from R7)
// ---------------------------------------------------------------------------
#define PJ_STAGE (3 * TILEB)
#define PJ_SMEM (2 * PJ_STAGE)

__global__ __launch_bounds__(256, 2)
void proj_gemm_kernel(const __half* __restrict__ A,
                      const __half* __restrict__ Bhi,
                      const __half* __restrict__ Blo,
                      const float* __restrict__ bias, float* __restrict__ C) {
    extern __shared__ char smem[];
    const uint32_t sb = smem_u32(smem);
    const int tid = threadIdx.x;
    const int warp = tid >> 5, lane = tid & 31;
    const int wm = warp >> 2, wn = warp & 3;
    const int bm = blockIdx.y * BM, bn = blockIdx.x * BN;

    float acc[4][4][4];
#pragma unroll
    for (int i = 0; i < 4; i++)
#pragma unroll
        for (int j = 0; j < 4; j++)
#pragma unroll
            for (int r = 0; r < 4; r++) acc[i][j][r] = 0.f;

    const __half* Abase = A + (size_t)bm * KTOT;
    const int a_r = lane & 15;
    const int a_c = (lane >> 4) * 16;
    const int b_lrow = lane & 7;
    const int b_q = lane >> 3;
    const int b_noff = ((b_q >> 1) * 8) + b_lrow;
    const int b_koff = (b_q & 1) * 16;

#define PJ_ISSUE(stg, k0)                                                        \
    do {                                                                         \
        _Pragma("unroll")                                                        \
        for (int i = 0; i < 12; i++) {                                           \
            int g = tid + 256 * i;                                               \
            int sel = g >> 10;                                                   \
            int r = g & 1023;                                                    \
            int row = r >> 3, k8 = r & 7;                                        \
            const __half* src =                                                  \
                (sel == 0 ? Abase + (size_t)row * KTOT                           \
                          : (sel == 1 ? Bhi : Blo) + (size_t)(bn + row) * KTOT)  \
                + (k0) + k8 * 8;                                                 \
            cp_async16((stg) + sel * TILEB + row * PITCHB + k8 * 16, src);       \
        }                                                                        \
        asm volatile("cp.async.commit_group;" ::: "memory");                     \
    } while (0)

    PJ_ISSUE(sb, 0);

    for (int c = 0; c < NCHUNK; c++) {
        const uint32_t sp = sb + (uint32_t)(c & 1) * PJ_STAGE;
        const bool pf = (c + 1 < NCHUNK);
        if (pf) PJ_ISSUE(sb + (uint32_t)((c + 1) & 1) * PJ_STAGE, (c + 1) * KC);
        if (pf) { asm volatile("cp.async.wait_group 1;" ::: "memory"); }
        else    { asm volatile("cp.async.wait_group 0;" ::: "memory"); }
        __syncthreads();

#pragma unroll
        for (int kk = 0; kk < 4; kk++) {
            const uint32_t kbyte = kk * 32;
            uint32_t Ar[4][4], Bh[2][4], Bl[2][4];
#pragma unroll
            for (int mt = 0; mt < 4; mt++)
                ldmx4(Ar[mt][0], Ar[mt][1], Ar[mt][2], Ar[mt][3],
                      sp + (wm * 64 + mt * 16 + a_r) * PITCHB + kbyte + a_c);
#pragma unroll
            for (int p = 0; p < 2; p++) {
                uint32_t bd = (wn * 32 + p * 16 + b_noff) * PITCHB + kbyte + b_koff;
                ldmx4(Bh[p][0], Bh[p][1], Bh[p][2], Bh[p][3], sp + TILEB + bd);
                ldmx4(Bl[p][0], Bl[p][1], Bl[p][2], Bl[p][3], sp + 2 * TILEB + bd);
            }
#pragma unroll
            for (int mt = 0; mt < 4; mt++)
#pragma unroll
                for (int nt = 0; nt < 4; nt++) {
                    const int p = nt >> 1, h = (nt & 1) * 2;
                    mma16816(acc[mt][nt], Ar[mt][0], Ar[mt][1], Ar[mt][2], Ar[mt][3],
                             Bh[p][h], Bh[p][h + 1]);
                    mma16816(acc[mt][nt], Ar[mt][0], Ar[mt][1], Ar[mt][2], Ar[mt][3],
                             Bl[p][h], Bl[p][h + 1]);
                }
        }
        __syncthreads();
    }

    const int gid = lane >> 2, tig = lane & 3;
#pragma unroll
    for (int mt = 0; mt < 4; mt++) {
        const int row = bm + wm * 64 + mt * 16 + gid;
#pragma unroll
        for (int nt = 0; nt < 4; nt++) {
            const int col = bn + wn * 32 + nt * 8 + tig * 2;
            const float b0 = bias[col], b1 = bias[col + 1];
            float2 v0 = make_float2(acc[mt][nt][0] + b0, acc[mt][nt][1] + b1);
            float2 v1 = make_float2(acc[mt][nt][2] + b0, acc[mt][nt][3] + b1);
            *(float2*)(C + (size_t)row * DIMC + col) = v0;
            *(float2*)(C + (size_t)(row + 8) * DIMC + col) = v1;
        }
    }
#undef PJ_ISSUE
}

// ---------------------------------------------------------------------------
// Tensor-core attention: block=(b,h), 4 warps; M,N padded to 64 tokens.
// smem: Q/K/V [64][32] fp16 pitch 80B; bi [64][66] fp32.
// ---------------------------------------------------------------------------
#define AQ_PITCH 80
#define ATN_TEN (64 * AQ_PITCH)           // 5120 per tensor
#define BI_PITCH 66

__global__ __launch_bounds__(128)
void attn_mma_kernel(const __half* __restrict__ qkv,
                     const float* __restrict__ bm,
                     __half* __restrict__ out) {
    __shared__ __align__(16) char sm[3 * ATN_TEN + 64 * BI_PITCH * 4];
    const uint32_t sb = smem_u32(sm);
    const uint32_t sQ = sb, sK = sb + ATN_TEN, sV = sb + 2 * ATN_TEN;
    const uint32_t sBI = sb + 3 * ATN_TEN;

    const int b = blockIdx.x, h = blockIdx.y;
    const int tid = threadIdx.x;
    const int warp = tid >> 5, lane = tid & 31;

    // zero pad rows 49..63 of Q/K/V (disjoint from cp.async targets)
    for (int idx = tid; idx < 225; idx += 128) {
        int t = idx / 75, rem = idx % 75;
        int row = 49 + rem / 5, ch = rem % 5;
        asm volatile("st.shared.v4.b32 [%0], {%1,%1,%1,%1};"
                     :: "r"(sQ + t * ATN_TEN + row * AQ_PITCH + ch * 16), "r"(0) : "memory");
    }
    // Q/K/V loads: 49 tokens x 3 tensors x 4 16B chunks
    const __half* base = qkv + (size_t)b * WIN * QKVC + h * HD;
    for (int idx = tid; idx < 588; idx += 128) {
        int i = idx / 12, rem = idx % 12;
        int sel = rem >> 2, ch = rem & 3;
        cp_async16(sQ + sel * ATN_TEN + i * AQ_PITCH + ch * 16,
                   base + (size_t)i * QKVC + sel * DIMC + ch * 8);
    }
    asm volatile("cp.async.commit_group;" ::: "memory");

    // bias+mask into smem, padded
    const float* bmrow = bm + (size_t)((b & (NWIN - 1)) * HEADS + h) * (WIN * WIN);
    for (int idx = tid; idx < 64 * 64; idx += 128) {
        int r = idx >> 6, c = idx & 63;
        float v = 0.f;
        if (r < WIN) v = (c < WIN) ? bmrow[r * WIN + c] : -1e30f;
        asm volatile("st.shared.b32 [%0], %1;"
                     :: "r"(sBI + (uint32_t)(r * BI_PITCH + c) * 4), "f"(v) : "memory");
    }
    asm volatile("cp.async.wait_group 0;" ::: "memory");
    __syncthreads();

    const int a_r = lane & 15;
    const int a_c = (lane >> 4) * 16;
    const int b_lrow = lane & 7;
    const int b_q = lane >> 3;
    const int b_noff = (b_q >> 1) * 8 + b_lrow;
    const int b_koff = (b_q & 1) * 16;

    // Q A-frags (2 k16 tiles)
    uint32_t Aq[2][4];
#pragma unroll
    for (int t = 0; t < 2; t++)
        ldmx4(Aq[t][0], Aq[t][1], Aq[t][2], Aq[t][3],
              sQ + (16 * warp + a_r) * AQ_PITCH + t * 32 + a_c);

    // scores S[8 n-tiles][4]
    float S[8][4];
#pragma unroll
    for (int i = 0; i < 8; i++)
#pragma unroll
        for (int r = 0; r < 4; r++) S[i][r] = 0.f;

#pragma unroll
    for (int p = 0; p < 4; p++)
#pragma unroll
        for (int t = 0; t < 2; t++) {
            uint32_t Bk[4];
            ldmx4(Bk[0], Bk[1], Bk[2], Bk[3],
                  sK + (16 * p + b_noff) * AQ_PITCH + t * 32 + b_koff);
            mma16816(S[2 * p],     Aq[t][0], Aq[t][1], Aq[t][2], Aq[t][3], Bk[0], Bk[1]);
            mma16816(S[2 * p + 1], Aq[t][0], Aq[t][1], Aq[t][2], Aq[t][3], Bk[2], Bk[3]);
        }

    // bias add
    const int gid = lane >> 2, tig = lane & 3;
    const int row0 = 16 * warp + gid;
#pragma unroll
    for (int nt = 0; nt < 8; nt++) {
        const uint32_t col4 = (uint32_t)(8 * nt + 2 * tig) * 4;
        float2 bv0, bv1;
        asm volatile("ld.shared.v2.f32 {%0,%1}, [%2];" : "=f"(bv0.x), "=f"(bv0.y)
                     : "r"(sBI + (uint32_t)row0 * BI_PITCH * 4 + col4));
        asm volatile("ld.shared.v2.f32 {%0,%1}, [%2];" : "=f"(bv1.x), "=f"(bv1.y)
                     : "r"(sBI + (uint32_t)(row0 + 8) * BI_PITCH * 4 + col4));
        S[nt][0] += bv0.x; S[nt][1] += bv0.y;
        S[nt][2] += bv1.x; S[nt][3] += bv1.y;
    }

    // softmax rows row0, row0+8
    float m0 = -3.0e38f, m1 = -3.0e38f;
#pragma unroll
    for (int nt = 0; nt < 8; nt++) {
        m0 = fmaxf(m0, fmaxf(S[nt][0], S[nt][1]));
        m1 = fmaxf(m1, fmaxf(S[nt][2], S[nt][3]));
    }
    m0 = fmaxf(m0, __shfl_xor_sync(0xffffffffu, m0, 1));
    m0 = fmaxf(m0, __shfl_xor_sync(0xffffffffu, m0, 2));
    m1 = fmaxf(m1, __shfl_xor_sync(0xffffffffu, m1, 1));
    m1 = fmaxf(m1, __shfl_xor_sync(0xffffffffu, m1, 2));

    float s0 = 0.f, s1 = 0.f;
#pragma unroll
    for (int nt = 0; nt < 8; nt++) {
        S[nt][0] = __expf(S[nt][0] - m0);
        S[nt][1] = __expf(S[nt][1] - m0);
        S[nt][2] = __expf(S[nt][2] - m1);
        S[nt][3] = __expf(S[nt][3] - m1);
        s0 += S[nt][0] + S[nt][1];
        s1 += S[nt][2] + S[nt][3];
    }
    s0 += __shfl_xor_sync(0xffffffffu, s0, 1);
    s0 += __shfl_xor_sync(0xffffffffu, s0, 2);
    s1 += __shfl_xor_sync(0xffffffffu, s1, 1);
    s1 += __shfl_xor_sync(0xffffffffu, s1, 2);
    const float inv0 = 1.0f / s0, inv1 = 1.0f / s1;

    // P fragments: C-layout pairs == A-frag layout for PV
    uint32_t P[4][4];
#pragma unroll
    for (int t = 0; t < 4; t++) {
        P[t][0] = pack2_f16(S[2 * t][0], S[2 * t][1]);
        P[t][1] = pack2_f16(S[2 * t][2], S[2 * t][3]);
        P[t][2] = pack2_f16(S[2 * t + 1][0], S[2 * t + 1][1]);
        P[t][3] = pack2_f16(S[2 * t + 1][2], S[2 * t + 1][3]);
    }

    // PV: O[4 n-tiles][4]
    float O[4][4];
#pragma unroll
    for (int i = 0; i < 4; i++)
#pragma unroll
        for (int r = 0; r < 4; r++) O[i][r] = 0.f;

    const uint32_t v_row = (uint32_t)((lane & 7) + 8 * ((lane >> 3) & 1));
    const uint32_t v_cb  = (uint32_t)((lane >> 4) * 16);
#pragma unroll
    for (int t = 0; t < 4; t++)
#pragma unroll
        for (int g = 0; g < 2; g++) {
            uint32_t Bv[4];
            ldmx4t(Bv[0], Bv[1], Bv[2], Bv[3],
                   sV + (16 * t + v_row) * AQ_PITCH + 32 * g + v_cb);
            mma16816(O[2 * g],     P[t][0], P[t][1], P[t][2], P[t][3], Bv[0], Bv[1]);
            mma16816(O[2 * g + 1], P[t][0], P[t][1], P[t][2], P[t][3], Bv[2], Bv[3]);
        }

    // store rows < 49, fp16
#pragma unroll
    for (int nt = 0; nt < 4; nt++) {
        const int col = h * HD + 8 * nt + 2 * tig;
        if (row0 < WIN) {
            __half2 v = __floats2half2_rn(O[nt][0] * inv0, O[nt][1] * inv0);
            *(__half2*)(out + ((size_t)b * WIN + row0) * DIMC + col) = v;
        }
        if (row0 + 8 < WIN) {
            __half2 v = __floats2half2_rn(O[nt][2] * inv1, O[nt][3] * inv1);
            *(__half2*)(out + ((size_t)b * WIN + row0 + 8) * DIMC + col) = v;
        }
    }
}

// ---------------------------------------------------------------------------
extern "C" void kernel_launch(void* const* d_in, const int* in_sizes, int n_in,
                              void* d_out, int out_size) {
    const float* x          = (const float*)d_in[0];
    const float* mask       = (const float*)d_in[1];
    const float* qkv_w      = (const float*)d_in[2];
    const float* qkv_b      = (const float*)d_in[3];
    const float* proj_w     = (const float*)d_in[4];
    const float* proj_b     = (const float*)d_in[5];
    const float* bias_table = (const float*)d_in[6];
    const int*   rel_index  = (const int*)d_in[7];
    float* out = (float*)d_out;

    __half *x16, *qkv, *att, *wq_hi, *wp_hi, *wp_lo;
    float* bmc;
    cudaGetSymbolAddress((void**)&x16, g_x16);
    cudaGetSymbolAddress((void**)&qkv, g_qkv);
    cudaGetSymbolAddress((void**)&att, g_att);
    cudaGetSymbolAddress((void**)&wq_hi, g_wqkv_hi);
    cudaGetSymbolAddress((void**)&wp_hi, g_wprj_hi);
    cudaGetSymbolAddress((void**)&wp_lo, g_wprj_lo);
    cudaGetSymbolAddress((void**)&bmc, g_bm);

    cudaFuncSetAttribute(qkv_gemm_kernel, cudaFuncAttributeMaxDynamicSharedMemorySize, QK_SMEM);
    cudaFuncSetAttribute(proj_gemm_kernel, cudaFuncAttributeMaxDynamicSharedMemorySize, PJ_SMEM);

    // 0) preps
    prep_x_kernel<<<(size_t)MROWS * KTOT / 4 / 256, 256>>>(x, x16);
    prep_w_kernel<<<(KTOT * QKVC + 255) / 256, 256>>>(qkv_w, wq_hi, nullptr, KTOT, QKVC, 0);
    prep_w_kernel<<<(KTOT * DIMC + 255) / 256, 256>>>(proj_w, wp_hi, wp_lo, KTOT, DIMC, 1);
    prep_bm_kernel<<<(NWIN * HEADS * WIN * WIN + 255) / 256, 256>>>(mask, bias_table,
                                                                    rel_index, bmc);
    // 1) qkv GEMM
    {
        dim3 grid(QKVC / BN, MROWS / BM);
        qkv_gemm_kernel<<<grid, 256, QK_SMEM>>>(x16, wq_hi, qkv_b, qkv);
    }
    // 2) tensor-core attention
    {
        dim3 grid(BATCH, HEADS);
        attn_mma_kernel<<<grid, 128>>>(qkv, bmc, att);
    }
    // 3) proj GEMM
    {
        dim3 grid(DIMC / BN, MROWS / BM);
        proj_gemm_kernel<<<grid, 256, PJ_SMEM>>>(att, wp_hi, wp_lo, proj_b, out);
    }
}

// round 9
// speedup vs baseline: 2.7394x; 1.6746x over previous
#include <cuda_runtime.h>
#include <cuda_fp16.h>
#include <cstdint>

#define WIN 49
#define HEADS 12
#define HD 32
#define DIMC 384
#define BATCH 4096
#define NWIN 64
#define QKVC (3 * DIMC)     // 1152
#define MROWS (BATCH * WIN) // 200704
#define KTOT 384

// ---------------- scratch (allocation-free rule: __device__ globals) -------
__device__ __half g_x16[(size_t)MROWS * KTOT];
__device__ __half g_qkv[(size_t)MROWS * QKVC];
__device__ __half g_att[(size_t)MROWS * DIMC];
__device__ __half g_wqkv_hi[QKVC * KTOT];
__device__ __half g_wprj_hi[DIMC * KTOT];
__device__ __half g_wprj_lo[DIMC * KTOT];
__device__ float  g_bm[(size_t)NWIN * HEADS * WIN * WIN]; // mask+bias combined

// ---------------- helpers ---------------------------------------------------
__device__ __forceinline__ uint32_t smem_u32(const void* p) {
    uint32_t a;
    asm("{ .reg .u64 t; cvta.to.shared.u64 t, %1; cvt.u32.u64 %0, t; }" : "=r"(a) : "l"(p));
    return a;
}
__device__ __forceinline__ uint32_t pack2_f16(float even, float odd) {
    uint32_t r;
    asm("cvt.rn.f16x2.f32 %0, %1, %2;" : "=r"(r) : "f"(odd), "f"(even));
    return r;
}
__device__ __forceinline__ void ldmx4(uint32_t& r0, uint32_t& r1, uint32_t& r2, uint32_t& r3,
                                      uint32_t addr) {
    asm volatile("ldmatrix.sync.aligned.m8n8.x4.shared.b16 {%0,%1,%2,%3}, [%4];"
                 : "=r"(r0), "=r"(r1), "=r"(r2), "=r"(r3) : "r"(addr));
}
__device__ __forceinline__ void ldmx4t(uint32_t& r0, uint32_t& r1, uint32_t& r2, uint32_t& r3,
                                       uint32_t addr) {
    asm volatile("ldmatrix.sync.aligned.m8n8.x4.trans.shared.b16 {%0,%1,%2,%3}, [%4];"
                 : "=r"(r0), "=r"(r1), "=r"(r2), "=r"(r3) : "r"(addr));
}
__device__ __forceinline__ void mma16816(float* d, uint32_t a0, uint32_t a1, uint32_t a2,
                                         uint32_t a3, uint32_t b0, uint32_t b1) {
    asm volatile(
        "mma.sync.aligned.m16n8k16.row.col.f32.f16.f16.f32 "
        "{%0,%1,%2,%3}, {%4,%5,%6,%7}, {%8,%9}, {%0,%1,%2,%3};"
        : "+f"(d[0]), "+f"(d[1]), "+f"(d[2]), "+f"(d[3])
        : "r"(a0), "r"(a1), "r"(a2), "r"(a3), "r"(b0), "r"(b1));
}
__device__ __forceinline__ void cp_async16(uint32_t saddr, const void* gaddr) {
    asm volatile("cp.async.cg.shared.global [%0], [%1], 16;" :: "r"(saddr), "l"(gaddr) : "memory");
}

// ---------------------------------------------------------------------------
// prep kernels
// ---------------------------------------------------------------------------
__global__ void prep_x_kernel(const float* __restrict__ X, __half* __restrict__ Y) {
    size_t idx = (size_t)blockIdx.x * 256 + threadIdx.x;
    float4 f = *(const float4*)(X + idx * 4);
    uint32_t h0 = pack2_f16(f.x, f.y), h1 = pack2_f16(f.z, f.w);
    *(uint2*)(Y + idx * 4) = make_uint2(h0, h1);
}

__global__ void prep_w_kernel(const float* __restrict__ W,
                              __half* __restrict__ hi,
                              __half* __restrict__ lo, int K, int N, int write_lo) {
    int idx = blockIdx.x * 256 + threadIdx.x;
    if (idx >= K * N) return;
    int k = idx / N, n = idx % N;
    float f = W[idx];
    __half h = __float2half_rn(f);
    hi[(size_t)n * K + k] = h;
    if (write_lo) lo[(size_t)n * K + k] = __float2half_rn(f - __half2float(h));
}

__global__ void prep_bm_kernel(const float* __restrict__ mask,
                               const float* __restrict__ bias_table,
                               const int* __restrict__ rel_index,
                               float* __restrict__ bm) {
    int idx = blockIdx.x * 256 + threadIdx.x;
    if (idx >= NWIN * HEADS * WIN * WIN) return;
    int rc = idx % (WIN * WIN);
    int nwh = idx / (WIN * WIN);
    int h = nwh % HEADS, nw = nwh / HEADS;
    bm[idx] = mask[nw * WIN * WIN + rc] + bias_table[rel_index[rc] * HEADS + h];
}

// ---------------------------------------------------------------------------
// Tile geometry (GEMMs)
// ---------------------------------------------------------------------------
#define BM 128
#define BN 128
#define KC 64
#define NCHUNK (KTOT / KC)
#define PITCHB 144
#define TILEB (128 * PITCHB)

// ---------------------------------------------------------------------------
// qkv GEMM: 1-term fp16, double-buffered cp.async
// ---------------------------------------------------------------------------
#define QK_STAGE (2 * TILEB)
#define QK_SMEM (2 * QK_STAGE)

__global__ __launch_bounds__(256, 2)
void qkv_gemm_kernel(const __half* __restrict__ A,
                     const __half* __restrict__ Bhi,
                     const float* __restrict__ bias, __half* __restrict__ C) {
    extern __shared__ char smem[];
    const uint32_t sb = smem_u32(smem);
    const int tid = threadIdx.x;
    const int warp = tid >> 5, lane = tid & 31;
    const int wm = warp >> 2, wn = warp & 3;
    const int bm = blockIdx.y * BM, bn = blockIdx.x * BN;

    float acc[4][4][4];
#pragma unroll
    for (int i = 0; i < 4; i++)
#pragma unroll
        for (int j = 0; j < 4; j++)
#pragma unroll
            for (int r = 0; r < 4; r++) acc[i][j][r] = 0.f;

    const __half* Abase = A + (size_t)bm * KTOT;
    const int a_r = lane & 15;
    const int a_c = (lane >> 4) * 16;
    const int b_lrow = lane & 7;
    const int b_q = lane >> 3;
    const int b_noff = ((b_q >> 1) * 8) + b_lrow;
    const int b_koff = (b_q & 1) * 16;

#define QK_ISSUE(stg, k0)                                                        \
    do {                                                                         \
        _Pragma("unroll")                                                        \
        for (int i = 0; i < 8; i++) {                                            \
            int g = tid + 256 * i;                                               \
            int sel = g >> 10;                                                   \
            int r = g & 1023;                                                    \
            int row = r >> 3, k8 = r & 7;                                        \
            const __half* src = (sel ? Bhi + (size_t)(bn + row) * KTOT           \
                                     : Abase + (size_t)row * KTOT) + (k0) + k8 * 8; \
            cp_async16((stg) + sel * TILEB + row * PITCHB + k8 * 16, src);       \
        }                                                                        \
        asm volatile("cp.async.commit_group;" ::: "memory");                     \
    } while (0)

    QK_ISSUE(sb, 0);

    for (int c = 0; c < NCHUNK; c++) {
        const uint32_t sp = sb + (uint32_t)(c & 1) * QK_STAGE;
        const bool pf = (c + 1 < NCHUNK);
        if (pf) QK_ISSUE(sb + (uint32_t)((c + 1) & 1) * QK_STAGE, (c + 1) * KC);
        if (pf) { asm volatile("cp.async.wait_group 1;" ::: "memory"); }
        else    { asm volatile("cp.async.wait_group 0;" ::: "memory"); }
        __syncthreads();

#pragma unroll
        for (int kk = 0; kk < 4; kk++) {
            const uint32_t kbyte = kk * 32;
            uint32_t Ar[4][4], Bh[2][4];
#pragma unroll
            for (int mt = 0; mt < 4; mt++)
                ldmx4(Ar[mt][0], Ar[mt][1], Ar[mt][2], Ar[mt][3],
                      sp + (wm * 64 + mt * 16 + a_r) * PITCHB + kbyte + a_c);
#pragma unroll
            for (int p = 0; p < 2; p++)
                ldmx4(Bh[p][0], Bh[p][1], Bh[p][2], Bh[p][3],
                      sp + TILEB + (wn * 32 + p * 16 + b_noff) * PITCHB + kbyte + b_koff);
#pragma unroll
            for (int mt = 0; mt < 4; mt++)
#pragma unroll
                for (int nt = 0; nt < 4; nt++) {
                    const int p = nt >> 1, h = (nt & 1) * 2;
                    mma16816(acc[mt][nt], Ar[mt][0], Ar[mt][1], Ar[mt][2], Ar[mt][3],
                             Bh[p][h], Bh[p][h + 1]);
                }
        }
        __syncthreads();
    }

    const int gid = lane >> 2, tig = lane & 3;
    const float qscale = 0.17677669529663687f;
#pragma unroll
    for (int mt = 0; mt < 4; mt++) {
        const int row = bm + wm * 64 + mt * 16 + gid;
#pragma unroll
        for (int nt = 0; nt < 4; nt++) {
            const int col = bn + wn * 32 + nt * 8 + tig * 2;
            const float b0 = bias[col], b1 = bias[col + 1];
            const float s = (col < DIMC) ? qscale : 1.0f;
            __half2 v0 = __floats2half2_rn((acc[mt][nt][0] + b0) * s, (acc[mt][nt][1] + b1) * s);
            __half2 v1 = __floats2half2_rn((acc[mt][nt][2] + b0) * s, (acc[mt][nt][3] + b1) * s);
            *(__half2*)(C + (size_t)row * QKVC + col) = v0;
            *(__half2*)(C + (size_t)(row + 8) * QKVC + col) = v1;
        }
    }
#undef QK_ISSUE
}

// ---------------------------------------------------------------------------
// proj GEMM: 2-term fp16, double-buffered cp.async
// ---------------------------------------------------------------------------
#define PJ_STAGE (3 * TILEB)
#define PJ_SMEM (2 * PJ_STAGE)

__global__ __launch_bounds__(256, 2)
void proj_gemm_kernel(const __half* __restrict__ A,
                      const __half* __restrict__ Bhi,
                      const __half* __restrict__ Blo,
                      const float* __restrict__ bias, float* __restrict__ C) {
    extern __shared__ char smem[];
    const uint32_t sb = smem_u32(smem);
    const int tid = threadIdx.x;
    const int warp = tid >> 5, lane = tid & 31;
    const int wm = warp >> 2, wn = warp & 3;
    const int bm = blockIdx.y * BM, bn = blockIdx.x * BN;

    float acc[4][4][4];
#pragma unroll
    for (int i = 0; i < 4; i++)
#pragma unroll
        for (int j = 0; j < 4; j++)
#pragma unroll
            for (int r = 0; r < 4; r++) acc[i][j][r] = 0.f;

    const __half* Abase = A + (size_t)bm * KTOT;
    const int a_r = lane & 15;
    const int a_c = (lane >> 4) * 16;
    const int b_lrow = lane & 7;
    const int b_q = lane >> 3;
    const int b_noff = ((b_q >> 1) * 8) + b_lrow;
    const int b_koff = (b_q & 1) * 16;

#define PJ_ISSUE(stg, k0)                                                        \
    do {                                                                         \
        _Pragma("unroll")                                                        \
        for (int i = 0; i < 12; i++) {                                           \
            int g = tid + 256 * i;                                               \
            int sel = g >> 10;                                                   \
            int r = g & 1023;                                                    \
            int row = r >> 3, k8 = r & 7;                                        \
            const __half* src =                                                  \
                (sel == 0 ? Abase + (size_t)row * KTOT                           \
                          : (sel == 1 ? Bhi : Blo) + (size_t)(bn + row) * KTOT)  \
                + (k0) + k8 * 8;                                                 \
            cp_async16((stg) + sel * TILEB + row * PITCHB + k8 * 16, src);       \
        }                                                                        \
        asm volatile("cp.async.commit_group;" ::: "memory");                     \
    } while (0)

    PJ_ISSUE(sb, 0);

    for (int c = 0; c < NCHUNK; c++) {
        const uint32_t sp = sb + (uint32_t)(c & 1) * PJ_STAGE;
        const bool pf = (c + 1 < NCHUNK);
        if (pf) PJ_ISSUE(sb + (uint32_t)((c + 1) & 1) * PJ_STAGE, (c + 1) * KC);
        if (pf) { asm volatile("cp.async.wait_group 1;" ::: "memory"); }
        else    { asm volatile("cp.async.wait_group 0;" ::: "memory"); }
        __syncthreads();

#pragma unroll
        for (int kk = 0; kk < 4; kk++) {
            const uint32_t kbyte = kk * 32;
            uint32_t Ar[4][4], Bh[2][4], Bl[2][4];
#pragma unroll
            for (int mt = 0; mt < 4; mt++)
                ldmx4(Ar[mt][0], Ar[mt][1], Ar[mt][2], Ar[mt][3],
                      sp + (wm * 64 + mt * 16 + a_r) * PITCHB + kbyte + a_c);
#pragma unroll
            for (int p = 0; p < 2; p++) {
                uint32_t bd = (wn * 32 + p * 16 + b_noff) * PITCHB + kbyte + b_koff;
                ldmx4(Bh[p][0], Bh[p][1], Bh[p][2], Bh[p][3], sp + TILEB + bd);
                ldmx4(Bl[p][0], Bl[p][1], Bl[p][2], Bl[p][3], sp + 2 * TILEB + bd);
            }
#pragma unroll
            for (int mt = 0; mt < 4; mt++)
#pragma unroll
                for (int nt = 0; nt < 4; nt++) {
                    const int p = nt >> 1, h = (nt & 1) * 2;
                    mma16816(acc[mt][nt], Ar[mt][0], Ar[mt][1], Ar[mt][2], Ar[mt][3],
                             Bh[p][h], Bh[p][h + 1]);
                    mma16816(acc[mt][nt], Ar[mt][0], Ar[mt][1], Ar[mt][2], Ar[mt][3],
                             Bl[p][h], Bl[p][h + 1]);
                }
        }
        __syncthreads();
    }

    const int gid = lane >> 2, tig = lane & 3;
#pragma unroll
    for (int mt = 0; mt < 4; mt++) {
        const int row = bm + wm * 64 + mt * 16 + gid;
#pragma unroll
        for (int nt = 0; nt < 4; nt++) {
            const int col = bn + wn * 32 + nt * 8 + tig * 2;
            const float b0 = bias[col], b1 = bias[col + 1];
            float2 v0 = make_float2(acc[mt][nt][0] + b0, acc[mt][nt][1] + b1);
            float2 v1 = make_float2(acc[mt][nt][2] + b0, acc[mt][nt][3] + b1);
            *(float2*)(C + (size_t)row * DIMC + col) = v0;
            *(float2*)(C + (size_t)(row + 8) * DIMC + col) = v1;
        }
    }
#undef PJ_ISSUE
}

// ---------------------------------------------------------------------------
// Tensor-core attention, amortized: block=(nw, h, img-group); bias loaded once
// into C-fragment registers; QKV double-buffered across GRP images.
// ---------------------------------------------------------------------------
#define AQ_PITCH 80
#define ATN_TEN (64 * AQ_PITCH)           // 5120 per tensor
#define ATN_STAGE (3 * ATN_TEN)           // Q,K,V
#define BI_PITCH 66
#define GRP 8

__global__ __launch_bounds__(128)
void attn_mma_kernel(const __half* __restrict__ qkv,
                     const float* __restrict__ bm,
                     __half* __restrict__ out) {
    __shared__ __align__(16) char sm[2 * ATN_STAGE + 64 * BI_PITCH * 4];
    const uint32_t sb = smem_u32(sm);
    const uint32_t sBI = sb + 2 * ATN_STAGE;

    const int nw = blockIdx.x, h = blockIdx.y;
    const int tid = threadIdx.x;
    const int warp = tid >> 5, lane = tid & 31;
    const int gid = lane >> 2, tig = lane & 3;
    const int row0 = 16 * warp + gid;

    // bias+mask -> smem (once per block)
    const float* bmrow = bm + (size_t)(nw * HEADS + h) * (WIN * WIN);
    for (int idx = tid; idx < 64 * 64; idx += 128) {
        int r = idx >> 6, c = idx & 63;
        float v = 0.f;
        if (r < WIN) v = (c < WIN) ? bmrow[r * WIN + c] : -1e30f;
        asm volatile("st.shared.b32 [%0], %1;"
                     :: "r"(sBI + (uint32_t)(r * BI_PITCH + c) * 4), "f"(v) : "memory");
    }
    // zero pad rows 49..63 of both stages' Q/K/V (written once; cp.async never touches)
    for (int idx = tid; idx < 450; idx += 128) {
        int st = idx / 225, rem = idx % 225;
        int t = rem / 75, r2 = rem % 75;
        int row = 49 + r2 / 5, ch = r2 % 5;
        asm volatile("st.shared.v4.b32 [%0], {%1,%1,%1,%1};"
                     :: "r"(sb + st * ATN_STAGE + t * ATN_TEN + row * AQ_PITCH + ch * 16),
                        "r"(0) : "memory");
    }
    __syncthreads();

    // lift bias into C-fragment registers
    float Sb[8][4];
#pragma unroll
    for (int nt = 0; nt < 8; nt++) {
        const uint32_t col4 = (uint32_t)(8 * nt + 2 * tig) * 4;
        asm volatile("ld.shared.v2.f32 {%0,%1}, [%2];" : "=f"(Sb[nt][0]), "=f"(Sb[nt][1])
                     : "r"(sBI + (uint32_t)row0 * BI_PITCH * 4 + col4));
        asm volatile("ld.shared.v2.f32 {%0,%1}, [%2];" : "=f"(Sb[nt][2]), "=f"(Sb[nt][3])
                     : "r"(sBI + (uint32_t)(row0 + 8) * BI_PITCH * 4 + col4));
    }

    const int a_r = lane & 15;
    const int a_c = (lane >> 4) * 16;
    const int b_lrow = lane & 7;
    const int b_q = lane >> 3;
    const int b_noff = (b_q >> 1) * 8 + b_lrow;
    const int b_koff = (b_q & 1) * 16;
    const uint32_t v_row = (uint32_t)((lane & 7) + 8 * ((lane >> 3) & 1));
    const uint32_t v_cb  = (uint32_t)((lane >> 4) * 16);

    const int img0 = blockIdx.z * GRP;

    // QKV issue for image ii into stage stg
#define AT_ISSUE(stg, ii)                                                         \
    do {                                                                          \
        const __half* base_ = qkv + ((size_t)((img0 + (ii)) * NWIN + nw) * WIN) * QKVC + h * HD; \
        _Pragma("unroll")                                                         \
        for (int u = 0; u < 5; u++) {                                             \
            int idx = tid + 128 * u;                                              \
            if (idx < 588) {                                                      \
                int i = idx / 12, rem = idx % 12;                                 \
                int sel = rem >> 2, ch = rem & 3;                                 \
                cp_async16((stg) + sel * ATN_TEN + i * AQ_PITCH + ch * 16,        \
                           base_ + (size_t)i * QKVC + sel * DIMC + ch * 8);       \
            }                                                                     \
        }                                                                         \
        asm volatile("cp.async.commit_group;" ::: "memory");                      \
    } while (0)

    AT_ISSUE(sb, 0);

    for (int ii = 0; ii < GRP; ii++) {
        const uint32_t sp = sb + (uint32_t)(ii & 1) * ATN_STAGE;
        const uint32_t sQ = sp, sK = sp + ATN_TEN, sV = sp + 2 * ATN_TEN;
        const bool pf = (ii + 1 < GRP);
        if (pf) AT_ISSUE(sb + (uint32_t)((ii + 1) & 1) * ATN_STAGE, ii + 1);
        if (pf) { asm volatile("cp.async.wait_group 1;" ::: "memory"); }
        else    { asm volatile("cp.async.wait_group 0;" ::: "memory"); }
        __syncthreads();

        // Q A-frags
        uint32_t Aq[2][4];
#pragma unroll
        for (int t = 0; t < 2; t++)
            ldmx4(Aq[t][0], Aq[t][1], Aq[t][2], Aq[t][3],
                  sQ + (16 * warp + a_r) * AQ_PITCH + t * 32 + a_c);

        // scores = bias + QK^T
        float S[8][4];
#pragma unroll
        for (int nt = 0; nt < 8; nt++)
#pragma unroll
            for (int r = 0; r < 4; r++) S[nt][r] = Sb[nt][r];

#pragma unroll
        for (int p = 0; p < 4; p++)
#pragma unroll
            for (int t = 0; t < 2; t++) {
                uint32_t Bk[4];
                ldmx4(Bk[0], Bk[1], Bk[2], Bk[3],
                      sK + (16 * p + b_noff) * AQ_PITCH + t * 32 + b_koff);
                mma16816(S[2 * p],     Aq[t][0], Aq[t][1], Aq[t][2], Aq[t][3], Bk[0], Bk[1]);
                mma16816(S[2 * p + 1], Aq[t][0], Aq[t][1], Aq[t][2], Aq[t][3], Bk[2], Bk[3]);
            }

        // softmax rows row0, row0+8
        float m0 = -3.0e38f, m1 = -3.0e38f;
#pragma unroll
        for (int nt = 0; nt < 8; nt++) {
            m0 = fmaxf(m0, fmaxf(S[nt][0], S[nt][1]));
            m1 = fmaxf(m1, fmaxf(S[nt][2], S[nt][3]));
        }
        m0 = fmaxf(m0, __shfl_xor_sync(0xffffffffu, m0, 1));
        m0 = fmaxf(m0, __shfl_xor_sync(0xffffffffu, m0, 2));
        m1 = fmaxf(m1, __shfl_xor_sync(0xffffffffu, m1, 1));
        m1 = fmaxf(m1, __shfl_xor_sync(0xffffffffu, m1, 2));

        float s0 = 0.f, s1 = 0.f;
#pragma unroll
        for (int nt = 0; nt < 8; nt++) {
            S[nt][0] = __expf(S[nt][0] - m0);
            S[nt][1] = __expf(S[nt][1] - m0);
            S[nt][2] = __expf(S[nt][2] - m1);
            S[nt][3] = __expf(S[nt][3] - m1);
            s0 += S[nt][0] + S[nt][1];
            s1 += S[nt][2] + S[nt][3];
        }
        s0 += __shfl_xor_sync(0xffffffffu, s0, 1);
        s0 += __shfl_xor_sync(0xffffffffu, s0, 2);
        s1 += __shfl_xor_sync(0xffffffffu, s1, 1);
        s1 += __shfl_xor_sync(0xffffffffu, s1, 2);
        const float inv0 = 1.0f / s0, inv1 = 1.0f / s1;

        // P fragments (C-layout == A-layout for PV)
        uint32_t P[4][4];
#pragma unroll
        for (int t = 0; t < 4; t++) {
            P[t][0] = pack2_f16(S[2 * t][0], S[2 * t][1]);
            P[t][1] = pack2_f16(S[2 * t][2], S[2 * t][3]);
            P[t][2] = pack2_f16(S[2 * t + 1][0], S[2 * t + 1][1]);
            P[t][3] = pack2_f16(S[2 * t + 1][2], S[2 * t + 1][3]);
        }

        float O[4][4];
#pragma unroll
        for (int i = 0; i < 4; i++)
#pragma unroll
            for (int r = 0; r < 4; r++) O[i][r] = 0.f;

#pragma unroll
        for (int t = 0; t < 4; t++)
#pragma unroll
            for (int g = 0; g < 2; g++) {
                uint32_t Bv[4];
                ldmx4t(Bv[0], Bv[1], Bv[2], Bv[3],
                       sV + (16 * t + v_row) * AQ_PITCH + 32 * g + v_cb);
                mma16816(O[2 * g],     P[t][0], P[t][1], P[t][2], P[t][3], Bv[0], Bv[1]);
                mma16816(O[2 * g + 1], P[t][0], P[t][1], P[t][2], P[t][3], Bv[2], Bv[3]);
            }

        const size_t ob = (size_t)((img0 + ii) * NWIN + nw) * WIN;
#pragma unroll
        for (int nt = 0; nt < 4; nt++) {
            const int col = h * HD + 8 * nt + 2 * tig;
            if (row0 < WIN) {
                __half2 v = __floats2half2_rn(O[nt][0] * inv0, O[nt][1] * inv0);
                *(__half2*)(out + (ob + row0) * DIMC + col) = v;
            }
            if (row0 + 8 < WIN) {
                __half2 v = __floats2half2_rn(O[nt][2] * inv1, O[nt][3] * inv1);
                *(__half2*)(out + (ob + row0 + 8) * DIMC + col) = v;
            }
        }
        __syncthreads();   // all warps done with stage before next issue reuses it
    }
#undef AT_ISSUE
}

// ---------------------------------------------------------------------------
extern "C" void kernel_launch(void* const* d_in, const int* in_sizes, int n_in,
                              void* d_out, int out_size) {
    const float* x          = (const float*)d_in[0];
    const float* mask       = (const float*)d_in[1];
    const float* qkv_w      = (const float*)d_in[2];
    const float* qkv_b      = (const float*)d_in[3];
    const float* proj_w     = (const float*)d_in[4];
    const float* proj_b     = (const float*)d_in[5];
    const float* bias_table = (const float*)d_in[6];
    const int*   rel_index  = (const int*)d_in[7];
    float* out = (float*)d_out;

    __half *x16, *qkv, *att, *wq_hi, *wp_hi, *wp_lo;
    float* bmc;
    cudaGetSymbolAddress((void**)&x16, g_x16);
    cudaGetSymbolAddress((void**)&qkv, g_qkv);
    cudaGetSymbolAddress((void**)&att, g_att);
    cudaGetSymbolAddress((void**)&wq_hi, g_wqkv_hi);
    cudaGetSymbolAddress((void**)&wp_hi, g_wprj_hi);
    cudaGetSymbolAddress((void**)&wp_lo, g_wprj_lo);
    cudaGetSymbolAddress((void**)&bmc, g_bm);

    cudaFuncSetAttribute(qkv_gemm_kernel, cudaFuncAttributeMaxDynamicSharedMemorySize, QK_SMEM);
    cudaFuncSetAttribute(proj_gemm_kernel, cudaFuncAttributeMaxDynamicSharedMemorySize, PJ_SMEM);

    // 0) preps
    prep_x_kernel<<<(size_t)MROWS * KTOT / 4 / 256, 256>>>(x, x16);
    prep_w_kernel<<<(KTOT * QKVC + 255) / 256, 256>>>(qkv_w, wq_hi, nullptr, KTOT, QKVC, 0);
    prep_w_kernel<<<(KTOT * DIMC + 255) / 256, 256>>>(proj_w, wp_hi, wp_lo, KTOT, DIMC, 1);
    prep_bm_kernel<<<(NWIN * HEADS * WIN * WIN + 255) / 256, 256>>>(mask, bias_table,
                                                                    rel_index, bmc);
    // 1) qkv GEMM
    {
        dim3 grid(QKVC / BN, MROWS / BM);
        qkv_gemm_kernel<<<grid, 256, QK_SMEM>>>(x16, wq_hi, qkv_b, qkv);
    }
    // 2) tensor-core attention (amortized bias, grouped images)
    {
        dim3 grid(NWIN, HEADS, BATCH / NWIN / GRP);
        attn_mma_kernel<<<grid, 128>>>(qkv, bmc, att);
    }
    // 3) proj GEMM
    {
        dim3 grid(DIMC / BN, MROWS / BM);
        proj_gemm_kernel<<<grid, 256, PJ_SMEM>>>(att, wp_hi, wp_lo, proj_b, out);
    }
}

// round 11
// speedup vs baseline: 3.0506x; 1.1136x over previous
#include <cuda_runtime.h>
#include <cuda_fp16.h>
#include <cstdint>

#define WIN 49
#define HEADS 12
#define HD 32
#define DIMC 384
#define BATCH 4096
#define NWIN 64
#define QKVC (3 * DIMC)     // 1152
#define MROWS (BATCH * WIN) // 200704
#define KTOT 384

// ---------------- scratch (allocation-free rule: __device__ globals) -------
__device__ __half g_x16[(size_t)MROWS * KTOT];
__device__ __half g_qkv[(size_t)MROWS * QKVC];
__device__ __half g_att[(size_t)MROWS * DIMC];
__device__ __half g_wqkv_hi[QKVC * KTOT];
__device__ __half g_wprj_hi[DIMC * KTOT];
__device__ float  g_bm[(size_t)NWIN * HEADS * WIN * WIN]; // mask+bias combined

// ---------------- helpers ---------------------------------------------------
__device__ __forceinline__ uint32_t smem_u32(const void* p) {
    uint32_t a;
    asm("{ .reg .u64 t; cvta.to.shared.u64 t, %1; cvt.u32.u64 %0, t; }" : "=r"(a) : "l"(p));
    return a;
}
__device__ __forceinline__ uint32_t pack2_f16(float even, float odd) {
    uint32_t r;
    asm("cvt.rn.f16x2.f32 %0, %1, %2;" : "=r"(r) : "f"(odd), "f"(even));
    return r;
}
__device__ __forceinline__ void ldmx4(uint32_t& r0, uint32_t& r1, uint32_t& r2, uint32_t& r3,
                                      uint32_t addr) {
    asm volatile("ldmatrix.sync.aligned.m8n8.x4.shared.b16 {%0,%1,%2,%3}, [%4];"
                 : "=r"(r0), "=r"(r1), "=r"(r2), "=r"(r3) : "r"(addr));
}
__device__ __forceinline__ void ldmx4t(uint32_t& r0, uint32_t& r1, uint32_t& r2, uint32_t& r3,
                                       uint32_t addr) {
    asm volatile("ldmatrix.sync.aligned.m8n8.x4.trans.shared.b16 {%0,%1,%2,%3}, [%4];"
                 : "=r"(r0), "=r"(r1), "=r"(r2), "=r"(r3) : "r"(addr));
}
__device__ __forceinline__ void mma16816(float* d, uint32_t a0, uint32_t a1, uint32_t a2,
                                         uint32_t a3, uint32_t b0, uint32_t b1) {
    asm volatile(
        "mma.sync.aligned.m16n8k16.row.col.f32.f16.f16.f32 "
        "{%0,%1,%2,%3}, {%4,%5,%6,%7}, {%8,%9}, {%0,%1,%2,%3};"
        : "+f"(d[0]), "+f"(d[1]), "+f"(d[2]), "+f"(d[3])
        : "r"(a0), "r"(a1), "r"(a2), "r"(a3), "r"(b0), "r"(b1));
}
__device__ __forceinline__ void cp_async16(uint32_t saddr, const void* gaddr) {
    asm volatile("cp.async.cg.shared.global [%0], [%1], 16;" :: "r"(saddr), "l"(gaddr) : "memory");
}

// ---------------------------------------------------------------------------
// prep kernels
// ---------------------------------------------------------------------------
__global__ void prep_x_kernel(const float* __restrict__ X, __half* __restrict__ Y) {
    size_t idx = (size_t)blockIdx.x * 256 + threadIdx.x;
    float4 f = *(const float4*)(X + idx * 4);
    uint32_t h0 = pack2_f16(f.x, f.y), h1 = pack2_f16(f.z, f.w);
    *(uint2*)(Y + idx * 4) = make_uint2(h0, h1);
}

__global__ void prep_w_kernel(const float* __restrict__ W,
                              __half* __restrict__ hi, int K, int N) {
    int idx = blockIdx.x * 256 + threadIdx.x;
    if (idx >= K * N) return;
    int k = idx / N, n = idx % N;
    hi[(size_t)n * K + k] = __float2half_rn(W[idx]);
}

__global__ void prep_bm_kernel(const float* __restrict__ mask,
                               const float* __restrict__ bias_table,
                               const int* __restrict__ rel_index,
                               float* __restrict__ bm) {
    int idx = blockIdx.x * 256 + threadIdx.x;
    if (idx >= NWIN * HEADS * WIN * WIN) return;
    int rc = idx % (WIN * WIN);
    int nwh = idx / (WIN * WIN);
    int h = nwh % HEADS, nw = nwh / HEADS;
    bm[idx] = mask[nw * WIN * WIN + rc] + bias_table[rel_index[rc] * HEADS + h];
}

// ---------------------------------------------------------------------------
// Tile geometry (GEMMs)
// ---------------------------------------------------------------------------
#define BM 128
#define BN 128
#define KC 64
#define NCHUNK (KTOT / KC)
#define PITCHB 144
#define TILEB (128 * PITCHB)

#define GM_STAGE (2 * TILEB)
#define GM_SMEM (2 * GM_STAGE)

// shared loader for a (A,W) stage
#define GM_ISSUE(stg, k0, Abase, Bhi, bn)                                        \
    do {                                                                         \
        _Pragma("unroll")                                                        \
        for (int i = 0; i < 8; i++) {                                            \
            int g = tid + 256 * i;                                               \
            int sel = g >> 10;                                                   \
            int r = g & 1023;                                                    \
            int row = r >> 3, k8 = r & 7;                                        \
            const __half* src = (sel ? (Bhi) + (size_t)((bn) + row) * KTOT       \
                                     : (Abase) + (size_t)row * KTOT) + (k0) + k8 * 8; \
            cp_async16((stg) + sel * TILEB + row * PITCHB + k8 * 16, src);       \
        }                                                                        \
        asm volatile("cp.async.commit_group;" ::: "memory");                     \
    } while (0)

// ---------------------------------------------------------------------------
// qkv GEMM: 1-term fp16, double-buffered cp.async; C fp16 (q scaled)
// ---------------------------------------------------------------------------
__global__ __launch_bounds__(256, 2)
void qkv_gemm_kernel(const __half* __restrict__ A,
                     const __half* __restrict__ Bhi,
                     const float* __restrict__ bias, __half* __restrict__ C) {
    extern __shared__ char smem[];
    const uint32_t sb = smem_u32(smem);
    const int tid = threadIdx.x;
    const int warp = tid >> 5, lane = tid & 31;
    const int wm = warp >> 2, wn = warp & 3;
    const int bm = blockIdx.y * BM, bn = blockIdx.x * BN;

    float acc[4][4][4];
#pragma unroll
    for (int i = 0; i < 4; i++)
#pragma unroll
        for (int j = 0; j < 4; j++)
#pragma unroll
            for (int r = 0; r < 4; r++) acc[i][j][r] = 0.f;

    const __half* Abase = A + (size_t)bm * KTOT;
    const int a_r = lane & 15;
    const int a_c = (lane >> 4) * 16;
    const int b_lrow = lane & 7;
    const int b_q = lane >> 3;
    const int b_noff = ((b_q >> 1) * 8) + b_lrow;
    const int b_koff = (b_q & 1) * 16;

    GM_ISSUE(sb, 0, Abase, Bhi, bn);

    for (int c = 0; c < NCHUNK; c++) {
        const uint32_t sp = sb + (uint32_t)(c & 1) * GM_STAGE;
        const bool pf = (c + 1 < NCHUNK);
        if (pf) GM_ISSUE(sb + (uint32_t)((c + 1) & 1) * GM_STAGE, (c + 1) * KC, Abase, Bhi, bn);
        if (pf) { asm volatile("cp.async.wait_group 1;" ::: "memory"); }
        else    { asm volatile("cp.async.wait_group 0;" ::: "memory"); }
        __syncthreads();

#pragma unroll
        for (int kk = 0; kk < 4; kk++) {
            const uint32_t kbyte = kk * 32;
            uint32_t Ar[4][4], Bh[2][4];
#pragma unroll
            for (int mt = 0; mt < 4; mt++)
                ldmx4(Ar[mt][0], Ar[mt][1], Ar[mt][2], Ar[mt][3],
                      sp + (wm * 64 + mt * 16 + a_r) * PITCHB + kbyte + a_c);
#pragma unroll
            for (int p = 0; p < 2; p++)
                ldmx4(Bh[p][0], Bh[p][1], Bh[p][2], Bh[p][3],
                      sp + TILEB + (wn * 32 + p * 16 + b_noff) * PITCHB + kbyte + b_koff);
#pragma unroll
            for (int mt = 0; mt < 4; mt++)
#pragma unroll
                for (int nt = 0; nt < 4; nt++) {
                    const int p = nt >> 1, h = (nt & 1) * 2;
                    mma16816(acc[mt][nt], Ar[mt][0], Ar[mt][1], Ar[mt][2], Ar[mt][3],
                             Bh[p][h], Bh[p][h + 1]);
                }
        }
        __syncthreads();
    }

    const int gid = lane >> 2, tig = lane & 3;
    const float qscale = 0.17677669529663687f;
#pragma unroll
    for (int mt = 0; mt < 4; mt++) {
        const int row = bm + wm * 64 + mt * 16 + gid;
#pragma unroll
        for (int nt = 0; nt < 4; nt++) {
            const int col = bn + wn * 32 + nt * 8 + tig * 2;
            const float b0 = bias[col], b1 = bias[col + 1];
            const float s = (col < DIMC) ? qscale : 1.0f;
            __half2 v0 = __floats2half2_rn((acc[mt][nt][0] + b0) * s, (acc[mt][nt][1] + b1) * s);
            __half2 v1 = __floats2half2_rn((acc[mt][nt][2] + b0) * s, (acc[mt][nt][3] + b1) * s);
            *(__half2*)(C + (size_t)row * QKVC + col) = v0;
            *(__half2*)(C + (size_t)(row + 8) * QKVC + col) = v1;
        }
    }
}

// ---------------------------------------------------------------------------
// proj GEMM: 1-term fp16, double-buffered cp.async; C fp32
// ---------------------------------------------------------------------------
__global__ __launch_bounds__(256, 2)
void proj_gemm_kernel(const __half* __restrict__ A,
                      const __half* __restrict__ Bhi,
                      const float* __restrict__ bias, float* __restrict__ C) {
    extern __shared__ char smem[];
    const uint32_t sb = smem_u32(smem);
    const int tid = threadIdx.x;
    const int warp = tid >> 5, lane = tid & 31;
    const int wm = warp >> 2, wn = warp & 3;
    const int bm = blockIdx.y * BM, bn = blockIdx.x * BN;

    float acc[4][4][4];
#pragma unroll
    for (int i = 0; i < 4; i++)
#pragma unroll
        for (int j = 0; j < 4; j++)
#pragma unroll
            for (int r = 0; r < 4; r++) acc[i][j][r] = 0.f;

    const __half* Abase = A + (size_t)bm * KTOT;
    const int a_r = lane & 15;
    const int a_c = (lane >> 4) * 16;
    const int b_lrow = lane & 7;
    const int b_q = lane >> 3;
    const int b_noff = ((b_q >> 1) * 8) + b_lrow;
    const int b_koff = (b_q & 1) * 16;

    GM_ISSUE(sb, 0, Abase, Bhi, bn);

    for (int c = 0; c < NCHUNK; c++) {
        const uint32_t sp = sb + (uint32_t)(c & 1) * GM_STAGE;
        const bool pf = (c + 1 < NCHUNK);
        if (pf) GM_ISSUE(sb + (uint32_t)((c + 1) & 1) * GM_STAGE, (c + 1) * KC, Abase, Bhi, bn);
        if (pf) { asm volatile("cp.async.wait_group 1;" ::: "memory"); }
        else    { asm volatile("cp.async.wait_group 0;" ::: "memory"); }
        __syncthreads();

#pragma unroll
        for (int kk = 0; kk < 4; kk++) {
            const uint32_t kbyte = kk * 32;
            uint32_t Ar[4][4], Bh[2][4];
#pragma unroll
            for (int mt = 0; mt < 4; mt++)
                ldmx4(Ar[mt][0], Ar[mt][1], Ar[mt][2], Ar[mt][3],
                      sp + (wm * 64 + mt * 16 + a_r) * PITCHB + kbyte + a_c);
#pragma unroll
            for (int p = 0; p < 2; p++)
                ldmx4(Bh[p][0], Bh[p][1], Bh[p][2], Bh[p][3],
                      sp + TILEB + (wn * 32 + p * 16 + b_noff) * PITCHB + kbyte + b_koff);
#pragma unroll
            for (int mt = 0; mt < 4; mt++)
#pragma unroll
                for (int nt = 0; nt < 4; nt++) {
                    const int p = nt >> 1, h = (nt & 1) * 2;
                    mma16816(acc[mt][nt], Ar[mt][0], Ar[mt][1], Ar[mt][2], Ar[mt][3],
                             Bh[p][h], Bh[p][h + 1]);
                }
        }
        __syncthreads();
    }

    const int gid = lane >> 2, tig = lane & 3;
#pragma unroll
    for (int mt = 0; mt < 4; mt++) {
        const int row = bm + wm * 64 + mt * 16 + gid;
#pragma unroll
        for (int nt = 0; nt < 4; nt++) {
            const int col = bn + wn * 32 + nt * 8 + tig * 2;
            const float b0 = bias[col], b1 = bias[col + 1];
            float2 v0 = make_float2(acc[mt][nt][0] + b0, acc[mt][nt][1] + b1);
            float2 v1 = make_float2(acc[mt][nt][2] + b0, acc[mt][nt][3] + b1);
            *(float2*)(C + (size_t)row * DIMC + col) = v0;
            *(float2*)(C + (size_t)(row + 8) * DIMC + col) = v1;
        }
    }
}

// ---------------------------------------------------------------------------
// Tensor-core attention, amortized (unchanged from round 9)
// ---------------------------------------------------------------------------
#define AQ_PITCH 80
#define ATN_TEN (64 * AQ_PITCH)
#define ATN_STAGE (3 * ATN_TEN)
#define BI_PITCH 66
#define GRP 8

__global__ __launch_bounds__(128)
void attn_mma_kernel(const __half* __restrict__ qkv,
                     const float* __restrict__ bm,
                     __half* __restrict__ out) {
    __shared__ __align__(16) char sm[2 * ATN_STAGE + 64 * BI_PITCH * 4];
    const uint32_t sb = smem_u32(sm);
    const uint32_t sBI = sb + 2 * ATN_STAGE;

    const int nw = blockIdx.x, h = blockIdx.y;
    const int tid = threadIdx.x;
    const int warp = tid >> 5, lane = tid & 31;
    const int gid = lane >> 2, tig = lane & 3;
    const int row0 = 16 * warp + gid;

    const float* bmrow = bm + (size_t)(nw * HEADS + h) * (WIN * WIN);
    for (int idx = tid; idx < 64 * 64; idx += 128) {
        int r = idx >> 6, c = idx & 63;
        float v = 0.f;
        if (r < WIN) v = (c < WIN) ? bmrow[r * WIN + c] : -1e30f;
        asm volatile("st.shared.b32 [%0], %1;"
                     :: "r"(sBI + (uint32_t)(r * BI_PITCH + c) * 4), "f"(v) : "memory");
    }
    for (int idx = tid; idx < 450; idx += 128) {
        int st = idx / 225, rem = idx % 225;
        int t = rem / 75, r2 = rem % 75;
        int row = 49 + r2 / 5, ch = r2 % 5;
        asm volatile("st.shared.v4.b32 [%0], {%1,%1,%1,%1};"
                     :: "r"(sb + st * ATN_STAGE + t * ATN_TEN + row * AQ_PITCH + ch * 16),
                        "r"(0) : "memory");
    }
    __syncthreads();

    float Sb[8][4];
#pragma unroll
    for (int nt = 0; nt < 8; nt++) {
        const uint32_t col4 = (uint32_t)(8 * nt + 2 * tig) * 4;
        asm volatile("ld.shared.v2.f32 {%0,%1}, [%2];" : "=f"(Sb[nt][0]), "=f"(Sb[nt][1])
                     : "r"(sBI + (uint32_t)row0 * BI_PITCH * 4 + col4));
        asm volatile("ld.shared.v2.f32 {%0,%1}, [%2];" : "=f"(Sb[nt][2]), "=f"(Sb[nt][3])
                     : "r"(sBI + (uint32_t)(row0 + 8) * BI_PITCH * 4 + col4));
    }

    const int a_r = lane & 15;
    const int a_c = (lane >> 4) * 16;
    const int b_lrow = lane & 7;
    const int b_q = lane >> 3;
    const int b_noff = (b_q >> 1) * 8 + b_lrow;
    const int b_koff = (b_q & 1) * 16;
    const uint32_t v_row = (uint32_t)((lane & 7) + 8 * ((lane >> 3) & 1));
    const uint32_t v_cb  = (uint32_t)((lane >> 4) * 16);

    const int img0 = blockIdx.z * GRP;

#define AT_ISSUE(stg, ii)                                                         \
    do {                                                                          \
        const __half* base_ = qkv + ((size_t)((img0 + (ii)) * NWIN + nw) * WIN) * QKVC + h * HD; \
        _Pragma("unroll")                                                         \
        for (int u = 0; u < 5; u++) {                                             \
            int idx = tid + 128 * u;                                              \
            if (idx < 588) {                                                      \
                int i = idx / 12, rem = idx % 12;                                 \
                int sel = rem >> 2, ch = rem & 3;                                 \
                cp_async16((stg) + sel * ATN_TEN + i * AQ_PITCH + ch * 16,        \
                           base_ + (size_t)i * QKVC + sel * DIMC + ch * 8);       \
            }                                                                     \
        }                                                                         \
        asm volatile("cp.async.commit_group;" ::: "memory");                      \
    } while (0)

    AT_ISSUE(sb, 0);

    for (int ii = 0; ii < GRP; ii++) {
        const uint32_t sp = sb + (uint32_t)(ii & 1) * ATN_STAGE;
        const uint32_t sQ = sp, sK = sp + ATN_TEN, sV = sp + 2 * ATN_TEN;
        const bool pf = (ii + 1 < GRP);
        if (pf) AT_ISSUE(sb + (uint32_t)((ii + 1) & 1) * ATN_STAGE, ii + 1);
        if (pf) { asm volatile("cp.async.wait_group 1;" ::: "memory"); }
        else    { asm volatile("cp.async.wait_group 0;" ::: "memory"); }
        __syncthreads();

        uint32_t Aq[2][4];
#pragma unroll
        for (int t = 0; t < 2; t++)
            ldmx4(Aq[t][0], Aq[t][1], Aq[t][2], Aq[t][3],
                  sQ + (16 * warp + a_r) * AQ_PITCH + t * 32 + a_c);

        float S[8][4];
#pragma unroll
        for (int nt = 0; nt < 8; nt++)
#pragma unroll
            for (int r = 0; r < 4; r++) S[nt][r] = Sb[nt][r];

#pragma unroll
        for (int p = 0; p < 4; p++)
#pragma unroll
            for (int t = 0; t < 2; t++) {
                uint32_t Bk[4];
                ldmx4(Bk[0], Bk[1], Bk[2], Bk[3],
                      sK + (16 * p + b_noff) * AQ_PITCH + t * 32 + b_koff);
                mma16816(S[2 * p],     Aq[t][0], Aq[t][1], Aq[t][2], Aq[t][3], Bk[0], Bk[1]);
                mma16816(S[2 * p + 1], Aq[t][0], Aq[t][1], Aq[t][2], Aq[t][3], Bk[2], Bk[3]);
            }

        float m0 = -3.0e38f, m1 = -3.0e38f;
#pragma unroll
        for (int nt = 0; nt < 8; nt++) {
            m0 = fmaxf(m0, fmaxf(S[nt][0], S[nt][1]));
            m1 = fmaxf(m1, fmaxf(S[nt][2], S[nt][3]));
        }
        m0 = fmaxf(m0, __shfl_xor_sync(0xffffffffu, m0, 1));
        m0 = fmaxf(m0, __shfl_xor_sync(0xffffffffu, m0, 2));
        m1 = fmaxf(m1, __shfl_xor_sync(0xffffffffu, m1, 1));
        m1 = fmaxf(m1, __shfl_xor_sync(0xffffffffu, m1, 2));

        float s0 = 0.f, s1 = 0.f;
#pragma unroll
        for (int nt = 0; nt < 8; nt++) {
            S[nt][0] = __expf(S[nt][0] - m0);
            S[nt][1] = __expf(S[nt][1] - m0);
            S[nt][2] = __expf(S[nt][2] - m1);
            S[nt][3] = __expf(S[nt][3] - m1);
            s0 += S[nt][0] + S[nt][1];
            s1 += S[nt][2] + S[nt][3];
        }
        s0 += __shfl_xor_sync(0xffffffffu, s0, 1);
        s0 += __shfl_xor_sync(0xffffffffu, s0, 2);
        s1 += __shfl_xor_sync(0xffffffffu, s1, 1);
        s1 += __shfl_xor_sync(0xffffffffu, s1, 2);
        const float inv0 = 1.0f / s0, inv1 = 1.0f / s1;

        uint32_t P[4][4];
#pragma unroll
        for (int t = 0; t < 4; t++) {
            P[t][0] = pack2_f16(S[2 * t][0], S[2 * t][1]);
            P[t][1] = pack2_f16(S[2 * t][2], S[2 * t][3]);
            P[t][2] = pack2_f16(S[2 * t + 1][0], S[2 * t + 1][1]);
            P[t][3] = pack2_f16(S[2 * t + 1][2], S[2 * t + 1][3]);
        }

        float O[4][4];
#pragma unroll
        for (int i = 0; i < 4; i++)
#pragma unroll
            for (int r = 0; r < 4; r++) O[i][r] = 0.f;

#pragma unroll
        for (int t = 0; t < 4; t++)
#pragma unroll
            for (int g = 0; g < 2; g++) {
                uint32_t Bv[4];
                ldmx4t(Bv[0], Bv[1], Bv[2], Bv[3],
                       sV + (16 * t + v_row) * AQ_PITCH + 32 * g + v_cb);
                mma16816(O[2 * g],     P[t][0], P[t][1], P[t][2], P[t][3], Bv[0], Bv[1]);
                mma16816(O[2 * g + 1], P[t][0], P[t][1], P[t][2], P[t][3], Bv[2], Bv[3]);
            }

        const size_t ob = (size_t)((img0 + ii) * NWIN + nw) * WIN;
#pragma unroll
        for (int nt = 0; nt < 4; nt++) {
            const int col = h * HD + 8 * nt + 2 * tig;
            if (row0 < WIN) {
                __half2 v = __floats2half2_rn(O[nt][0] * inv0, O[nt][1] * inv0);
                *(__half2*)(out + (ob + row0) * DIMC + col) = v;
            }
            if (row0 + 8 < WIN) {
                __half2 v = __floats2half2_rn(O[nt][2] * inv1, O[nt][3] * inv1);
                *(__half2*)(out + (ob + row0 + 8) * DIMC + col) = v;
            }
        }
        __syncthreads();
    }
#undef AT_ISSUE
}

// ---------------------------------------------------------------------------
extern "C" void kernel_launch(void* const* d_in, const int* in_sizes, int n_in,
                              void* d_out, int out_size) {
    const float* x          = (const float*)d_in[0];
    const float* mask       = (const float*)d_in[1];
    const float* qkv_w      = (const float*)d_in[2];
    const float* qkv_b      = (const float*)d_in[3];
    const float* proj_w     = (const float*)d_in[4];
    const float* proj_b     = (const float*)d_in[5];
    const float* bias_table = (const float*)d_in[6];
    const int*   rel_index  = (const int*)d_in[7];
    float* out = (float*)d_out;

    __half *x16, *qkv, *att, *wq_hi, *wp_hi;
    float* bmc;
    cudaGetSymbolAddress((void**)&x16, g_x16);
    cudaGetSymbolAddress((void**)&qkv, g_qkv);
    cudaGetSymbolAddress((void**)&att, g_att);
    cudaGetSymbolAddress((void**)&wq_hi, g_wqkv_hi);
    cudaGetSymbolAddress((void**)&wp_hi, g_wprj_hi);
    cudaGetSymbolAddress((void**)&bmc, g_bm);

    cudaFuncSetAttribute(qkv_gemm_kernel, cudaFuncAttributeMaxDynamicSharedMemorySize, GM_SMEM);
    cudaFuncSetAttribute(proj_gemm_kernel, cudaFuncAttributeMaxDynamicSharedMemorySize, GM_SMEM);

    // 0) preps
    prep_x_kernel<<<(size_t)MROWS * KTOT / 4 / 256, 256>>>(x, x16);
    prep_w_kernel<<<(KTOT * QKVC + 255) / 256, 256>>>(qkv_w, wq_hi, KTOT, QKVC);
    prep_w_kernel<<<(KTOT * DIMC + 255) / 256, 256>>>(proj_w, wp_hi, KTOT, DIMC);
    prep_bm_kernel<<<(NWIN * HEADS * WIN * WIN + 255) / 256, 256>>>(mask, bias_table,
                                                                    rel_index, bmc);
    // 1) qkv GEMM (1-term)
    {
        dim3 grid(QKVC / BN, MROWS / BM);
        qkv_gemm_kernel<<<grid, 256, GM_SMEM>>>(x16, wq_hi, qkv_b, qkv);
    }
    // 2) tensor-core attention
    {
        dim3 grid(NWIN, HEADS, BATCH / NWIN / GRP);
        attn_mma_kernel<<<grid, 128>>>(qkv, bmc, att);
    }
    // 3) proj GEMM (1-term)
    {
        dim3 grid(DIMC / BN, MROWS / BM);
        proj_gemm_kernel<<<grid, 256, GM_SMEM>>>(att, wp_hi, proj_b, out);
    }
}